// round 10
// baseline (speedup 1.0000x reference)
#include <cuda_runtime.h>
#include <cuda_fp16.h>
#include <cstdint>
#include <math.h>

// ---------------- scratch ----------------
__device__ __half g_kbuf[8 * 16 * 1024 * 32];   // [n][h][l][d]
__device__ __half g_qbuf[8 * 16 * 1024 * 32];   // [n][h][l][d] (pre-scaled 1/32)
__device__ __half g_vbuf[8 * 1024 * 1024];      // [n][c][l]
__device__ float  g_t2 [8 * 1024 * 1024];       // [n][c][l] fp32 residual
__device__ __half g_t2T[8 * 1024 * 1024];       // [n][l][c]
__device__ __half g_tokT[8 * 1024 * 1024];      // [n][l][c]
__device__ __half g_wg[8 * 256 * 128];          // [g][r][k]
__device__ float  g_bg[8 * 256];
__device__ __half g_wf[1024 * 1024];            // [c][k]
__device__ float  g_bf[1024];

// ---------------- helpers ----------------
__device__ __forceinline__ uint32_t smem_u32(const void* p) {
    uint32_t a;
    asm("{ .reg .u64 t; cvta.to.shared.u64 t, %1; cvt.u32.u64 %0, t; }" : "=r"(a) : "l"(p));
    return a;
}
#define CPA(dst, src) asm volatile("cp.async.cg.shared.global [%0], [%1], 16;" :: "r"(dst), "l"(__cvta_generic_to_global(src)))
#define CPC()  asm volatile("cp.async.commit_group;" ::: "memory")
#define CPW0() asm volatile("cp.async.wait_group 0;" ::: "memory")
#define CPW1() asm volatile("cp.async.wait_group 1;" ::: "memory")
#define CPW2() asm volatile("cp.async.wait_group 2;" ::: "memory")
#define LDSM4(r0, r1, r2, r3, a) \
    asm volatile("ldmatrix.sync.aligned.m8n8.x4.shared.b16 {%0,%1,%2,%3}, [%4];" \
        : "=r"(r0), "=r"(r1), "=r"(r2), "=r"(r3) : "r"(a))

__device__ __forceinline__ void mma16(float* d, const uint32_t* a, uint32_t b0, uint32_t b1) {
    asm volatile(
        "mma.sync.aligned.m16n8k16.row.col.f32.f16.f16.f32 "
        "{%0,%1,%2,%3}, {%4,%5,%6,%7}, {%8,%9}, {%0,%1,%2,%3};"
        : "+f"(d[0]), "+f"(d[1]), "+f"(d[2]), "+f"(d[3])
        : "r"(a[0]), "r"(a[1]), "r"(a[2]), "r"(a[3]), "r"(b0), "r"(b1));
}
__device__ __forceinline__ uint32_t packh2(float a, float b) {
    __half2 h = __floats2half2_rn(a, b);
    return *(uint32_t*)&h;
}
__device__ __forceinline__ float ex2f(float x) {
    float r;
    asm("ex2.approx.f32 %0, %1;" : "=f"(r) : "f"(x));
    return r;
}
#define L2E 1.4426950408889634f

// ---------------- fused prep + tokens transpose ----------------
#define TRANS_BLOCKS 8192
__global__ __launch_bounds__(256) void prep_kernel(
    const float* __restrict__ tokens,
    const float* __restrict__ kw, const float* __restrict__ kb, const float* __restrict__ kga,
    const float* __restrict__ kbe, const float* __restrict__ km, const float* __restrict__ kv,
    const float* __restrict__ qw, const float* __restrict__ qb, const float* __restrict__ qga,
    const float* __restrict__ qbe, const float* __restrict__ qm, const float* __restrict__ qv,
    const float* __restrict__ vw, const float* __restrict__ vb, const float* __restrict__ vga,
    const float* __restrict__ vbe, const float* __restrict__ vm, const float* __restrict__ vv,
    const float* __restrict__ fw, const float* __restrict__ fb, const float* __restrict__ fga,
    const float* __restrict__ fbe, const float* __restrict__ fm, const float* __restrict__ fv)
{
    __shared__ float tile[32][33];
    int t = threadIdx.x;
    if (blockIdx.x < TRANS_BLOCKS) {
        int bid = blockIdx.x;
        int l0 = (bid & 31) * 32, c0 = ((bid >> 5) & 31) * 32, n = bid >> 10;
#pragma unroll
        for (int i = 0; i < 4; ++i) {
            int idx = i * 256 + t;
            int r = idx >> 5, col = idx & 31;
            tile[r][col] = tokens[((size_t)(n * 1024 + c0 + r)) * 1024 + l0 + col];
        }
        __syncthreads();
#pragma unroll
        for (int i = 0; i < 4; ++i) {
            int idx = i * 256 + t;
            int r = idx >> 5, col = idx & 31;
            g_tokT[((size_t)(n * 1024 + l0 + r)) * 1024 + c0 + col] = __float2half(tile[col][r]);
        }
        return;
    }
    int id = (blockIdx.x - TRANS_BLOCKS) * 256 + t;
    if (id < 1024 * 1024) {
        int c = id >> 10;
        float inv = fga[c] * rsqrtf(fv[c] + 1e-5f);
        g_wf[id] = __float2half(fw[id] * inv);
        return;
    }
    int id2 = id - 1024 * 1024;
    if (id2 < 8 * 256 * 128) {
        int k = id2 & 127;
        int r = (id2 >> 7) & 255;
        int g = id2 >> 15;
        float w;
        if (r < 64) {
            int c = g * 64 + r;
            float inv = kga[c] * rsqrtf(kv[c] + 1e-5f);
            w = kw[c * 128 + k] * inv;
        } else if (r < 128) {
            int c = g * 64 + (r - 64);
            float inv = qga[c] * rsqrtf(qv[c] + 1e-5f);
            w = qw[c * 128 + k] * inv * 0.03125f;
        } else {
            int c = g * 128 + (r - 128);
            float inv = vga[c] * rsqrtf(vv[c] + 1e-5f);
            w = vw[c * 128 + k] * inv;
        }
        g_wg[id2] = __float2half(w);
        return;
    }
    int id3 = id2 - 8 * 256 * 128;
    if (id3 < 8 * 256) {
        int g = id3 >> 8, r = id3 & 255;
        float bias;
        if (r < 64) {
            int c = g * 64 + r;
            float inv = kga[c] * rsqrtf(kv[c] + 1e-5f);
            bias = kb[c] * inv + kbe[c] - km[c] * inv;
        } else if (r < 128) {
            int c = g * 64 + (r - 64);
            float inv = qga[c] * rsqrtf(qv[c] + 1e-5f);
            bias = (qb[c] * inv + qbe[c] - qm[c] * inv) * 0.03125f;
        } else {
            int c = g * 128 + (r - 128);
            float inv = vga[c] * rsqrtf(vv[c] + 1e-5f);
            bias = vb[c] * inv + vbe[c] - vm[c] * inv;
        }
        g_bg[id3] = bias;
        return;
    }
    int c = id3 - 8 * 256;
    if (c < 1024) {
        float inv = fga[c] * rsqrtf(fv[c] + 1e-5f);
        g_bf[c] = fb[c] * inv + fbe[c] - fm[c] * inv;
    }
}

// ---------------- GEMM pieces (fp16, ldmatrix, K-chunk 64, padded pitch) ----------------
#define TP64 144u
#define GTILE 18432u
#define GSTG  36864u
#define GEMM_SMEM 110592
__device__ __forceinline__ void load_tile64(uint32_t dst, const __half* src, int stride_h, int t)
{
#pragma unroll
    for (int i = 0; i < 4; ++i) {
        int idx = i * 256 + t;
        int row = idx >> 3, c16 = idx & 7;
        CPA(dst + (uint32_t)row * TP64 + (uint32_t)c16 * 16u, src + (size_t)row * stride_h + c16 * 8);
    }
}

__device__ __forceinline__ void wgemm64(uint32_t As, uint32_t Bs, float C[4][4][4], int lane,
                                        int m0, int n0)
{
    int lr = (lane & 7) + ((lane >> 3) & 1) * 8;
    int akb = ((lane >> 4) & 1) * 8;
    int br = (lane & 7) + ((lane >> 4) & 1) * 8;
    int bkb = ((lane >> 3) & 1) * 8;
#pragma unroll
    for (int ks = 0; ks < 4; ++ks) {
        uint32_t a[4][4];
#pragma unroll
        for (int mi = 0; mi < 4; ++mi)
            LDSM4(a[mi][0], a[mi][1], a[mi][2], a[mi][3],
                  As + (uint32_t)(m0 + mi * 16 + lr) * TP64 + (uint32_t)((ks * 16 + akb) * 2));
#pragma unroll
        for (int np = 0; np < 2; ++np) {
            uint32_t b0, b1, b2, b3;
            LDSM4(b0, b1, b2, b3,
                  Bs + (uint32_t)(n0 + np * 16 + br) * TP64 + (uint32_t)((ks * 16 + bkb) * 2));
#pragma unroll
            for (int mi = 0; mi < 4; ++mi) {
                mma16(C[mi][np * 2], a[mi], b0, b1);
                mma16(C[mi][np * 2 + 1], a[mi], b2, b3);
            }
        }
    }
}

// ---------------- qkv conv GEMM (unchanged) ----------------
__global__ __launch_bounds__(256, 2) void qkv_tc()
{
    extern __shared__ float sm[];
    uint32_t sb = smem_u32(sm);
    int t = threadIdx.x, wid = t >> 5, lane = t & 31;
    int lt = blockIdx.x, rb = blockIdx.y, ng = blockIdx.z;
    int n = ng >> 3, g = ng & 7;
    int l0 = lt * 128;
    int m0 = (wid & 1) * 64, n0 = (wid >> 1) * 32;
    const __half* Ag = g_wg + (size_t)(g * 256 + rb * 128) * 128;
    const __half* Bg = g_tokT + ((size_t)(n * 1024 + l0)) * 1024 + g * 128;

    float C[4][4][4] = {};
    load_tile64(sb, Ag, 128, t);
    load_tile64(sb + GTILE, Bg, 1024, t);
    CPC();
    load_tile64(sb + GSTG, Ag + 64, 128, t);
    load_tile64(sb + GSTG + GTILE, Bg + 64, 1024, t);
    CPC();
    for (int c = 0; c < 2; ++c) {
        if (c == 0) CPW1(); else CPW0();
        __syncthreads();
        uint32_t As = sb + (uint32_t)c * GSTG;
        wgemm64(As, As + GTILE, C, lane, m0, n0);
    }
    __syncthreads();

    float* Sb = sm;  // [128][33]
    int r4 = lane >> 2, j = lane & 3;
    for (int ch = 0; ch < 4; ++ch) {
        if ((wid >> 1) == ch) {
#pragma unroll
            for (int mi = 0; mi < 4; ++mi)
#pragma unroll
                for (int ni = 0; ni < 4; ++ni) {
                    int m = m0 + mi * 16 + r4;
                    int q = ni * 8 + 2 * j;
                    Sb[m * 33 + q] = C[mi][ni][0];
                    Sb[m * 33 + q + 1] = C[mi][ni][1];
                    Sb[(m + 8) * 33 + q] = C[mi][ni][2];
                    Sb[(m + 8) * 33 + q + 1] = C[mi][ni][3];
                }
        }
        __syncthreads();
        if (rb == 0) {
#pragma unroll
            for (int i = 0; i < 8; ++i) {
                int m = t & 63, l = (t >> 6) + 4 * i;
                int h = 2 * g + (m >> 5), d = m & 31;
                size_t base = (((size_t)(n * 16 + h)) * 1024 + l0 + ch * 32 + l) * 32 + d;
                g_kbuf[base] = __float2half(Sb[m * 33 + l] + g_bg[g * 256 + m]);
                g_qbuf[base] = __float2half(Sb[(m + 64) * 33 + l] + g_bg[g * 256 + 64 + m]);
            }
        } else {
#pragma unroll
            for (int i = 0; i < 16; ++i) {
                int l = t & 31, m = (t >> 5) + 8 * i;
                g_vbuf[((size_t)(n * 1024 + g * 128 + m)) * 1024 + l0 + ch * 32 + l] =
                    __float2half(Sb[m * 33 + l] + g_bg[g * 256 + 128 + m]);
            }
        }
        __syncthreads();
    }
}

// ---------------- ff conv: 512 threads, 128x256 tile, 4-stage swizzled pipeline ----------------
// stage = A(128x64h swizzled, 16384B) + B(256x64h swizzled, 32768B) = 49152B; 4 stages = 196608
#define FA 16384u
#define FSTG 49152u
#define FCONV_SMEM 196608
#define SWA(row, ch) (((uint32_t)(row) << 7) + (uint32_t)(((ch) ^ ((row) & 7)) << 4))

__device__ __forceinline__ void fload(uint32_t base, const __half* Ag, const __half* Bg, int t)
{
#pragma unroll
    for (int i = 0; i < 2; ++i) {           // A: 1024 chunks
        int idx = i * 512 + t;
        int row = idx >> 3, ch = idx & 7;
        CPA(base + SWA(row, ch), Ag + (size_t)row * 1024 + ch * 8);
    }
#pragma unroll
    for (int i = 0; i < 4; ++i) {           // B: 2048 chunks
        int idx = i * 512 + t;
        int row = idx >> 3, ch = idx & 7;
        CPA(base + FA + SWA(row, ch), Bg + (size_t)row * 1024 + ch * 8);
    }
    CPC();
}

__global__ __launch_bounds__(512, 1) void fconv_tc(float* __restrict__ out)
{
    extern __shared__ float sm[];
    uint32_t sb = smem_u32(sm);
    int t = threadIdx.x, wid = t >> 5, lane = t & 31;
    int lt = blockIdx.x, cb = blockIdx.y, n = blockIdx.z;
    int l0 = lt * 256;
    int m0 = (wid & 1) * 64, n0 = (wid >> 1) * 32;
    const __half* Ag = g_wf + (size_t)(cb * 128) * 1024;
    const __half* Bg = g_t2T + ((size_t)(n * 1024 + l0)) * 1024;

    float C[4][4][4] = {};
    fload(sb, Ag, Bg, t);
    fload(sb + FSTG, Ag + 64, Bg + 64, t);
    fload(sb + 2 * FSTG, Ag + 128, Bg + 128, t);

    int lr = (lane & 7) + ((lane >> 3) & 1) * 8;
    int akb8 = (lane >> 4) & 1;              // A k-half (chunk offset)
    int br = (lane & 7) + ((lane >> 4) & 1) * 8;
    int bkb8 = (lane >> 3) & 1;

    for (int c = 0; c < 16; ++c) {
        if (c < 14) CPW2(); else if (c == 14) CPW1(); else CPW0();
        __syncthreads();
        if (c + 3 < 16)
            fload(sb + (uint32_t)((c + 3) & 3) * FSTG, Ag + (c + 3) * 64, Bg + (c + 3) * 64, t);
        uint32_t As = sb + (uint32_t)(c & 3) * FSTG;
        uint32_t Bs = As + FA;
#pragma unroll
        for (int ks = 0; ks < 4; ++ks) {
            uint32_t a[4][4];
#pragma unroll
            for (int mi = 0; mi < 4; ++mi) {
                int row = m0 + mi * 16 + lr;
                LDSM4(a[mi][0], a[mi][1], a[mi][2], a[mi][3], As + SWA(row, ks * 2 + akb8));
            }
#pragma unroll
            for (int np = 0; np < 2; ++np) {
                int row = n0 + np * 16 + br;
                uint32_t b0, b1, b2, b3;
                LDSM4(b0, b1, b2, b3, Bs + SWA(row, ks * 2 + bkb8));
#pragma unroll
                for (int mi = 0; mi < 4; ++mi) {
                    mma16(C[mi][np * 2], a[mi], b0, b1);
                    mma16(C[mi][np * 2 + 1], a[mi], b2, b3);
                }
            }
        }
    }
    __syncthreads();

    float* Sb = sm;   // [128][33] fp32
    int r4 = lane >> 2, j = lane & 3;
    for (int ch = 0; ch < 8; ++ch) {
        if ((wid >> 1) == ch) {
#pragma unroll
            for (int mi = 0; mi < 4; ++mi)
#pragma unroll
                for (int ni = 0; ni < 4; ++ni) {
                    int m = m0 + mi * 16 + r4;
                    int q = ni * 8 + 2 * j;
                    Sb[m * 33 + q] = C[mi][ni][0];
                    Sb[m * 33 + q + 1] = C[mi][ni][1];
                    Sb[(m + 8) * 33 + q] = C[mi][ni][2];
                    Sb[(m + 8) * 33 + q + 1] = C[mi][ni][3];
                }
        }
        __syncthreads();
#pragma unroll
        for (int i = 0; i < 8; ++i) {
            int l = t & 31, m = (t >> 5) + 16 * i;
            size_t addr = ((size_t)(n * 1024 + cb * 128 + m)) * 1024 + l0 + ch * 32 + l;
            out[addr] = Sb[m * 33 + l] + g_bf[cb * 128 + m] + g_t2[addr];
        }
        __syncthreads();
    }
}

// ---------------- flash attention: 4-stage, paired tiles (R9) ----------------
#define TPK 80u
#define KST 5120u
#define AST 14336u
#define ATTN_SMEM 57344

__device__ __forceinline__ void attn_load(uint32_t sb, const __half* Kg, const __half* Vg,
                                          int kt, int st, int t)
{
    uint32_t base = sb + (uint32_t)st * AST;
    int k0 = kt * 64;
    int row = t >> 2, c16 = t & 3;
    CPA(base + (uint32_t)row * TPK + (uint32_t)c16 * 16u, Kg + (size_t)(k0 + row) * 32 + c16 * 8);
#pragma unroll
    for (int i = 0; i < 2; ++i) {
        int idx = i * 256 + t;
        int vr = idx >> 3, vc = idx & 7;
        CPA(base + KST + (uint32_t)(vr * 144 + vc * 16), Vg + (size_t)vr * 1024 + k0 + vc * 8);
    }
    CPC();
}

__global__ __launch_bounds__(256, 2) void attn_tc(const float* __restrict__ tokens)
{
    extern __shared__ float sm[];
    uint32_t sb = smem_u32(sm);

    int t = threadIdx.x, wid = t >> 5, lane = t & 31;
    int r4 = lane >> 2, j = lane & 3;
    int qt = blockIdx.x, h = blockIdx.y, n = blockIdx.z;
    int q0g = qt * 128, q0w = wid * 16;
    const __half* Kg = g_kbuf + ((size_t)(n * 16 + h)) * 1024 * 32;
    const __half* Qg = g_qbuf + ((size_t)(n * 16 + h)) * 1024 * 32;
    const __half* Vg = g_vbuf + ((size_t)(n * 1024 + h * 64)) * 1024;

    uint32_t aq[2][4];
#pragma unroll
    for (int ds = 0; ds < 2; ++ds) {
        const __half* qb = Qg + (size_t)(q0g + q0w + r4) * 32 + ds * 16 + 2 * j;
        aq[ds][0] = *(const uint32_t*)qb;
        aq[ds][1] = *(const uint32_t*)(qb + 8 * 32);
        aq[ds][2] = *(const uint32_t*)(qb + 8);
        aq[ds][3] = *(const uint32_t*)(qb + 8 * 32 + 8);
    }

    attn_load(sb, Kg, Vg, 0, 0, t);
    attn_load(sb, Kg, Vg, 1, 1, t);

    float CO[8][4] = {};
    float mo0 = -1e30f, mo1 = -1e30f, l0 = 0.f, l1 = 0.f;
    int lr = (lane & 7) + ((lane >> 4) & 1) * 8;
    int kbo = ((lane >> 3) & 1) * 8;

    for (int pr = 0; pr < 8; ++pr) {
        CPW0();
        __syncthreads();
        if (pr < 7) {
            attn_load(sb, Kg, Vg, 2 * pr + 2, (2 * pr + 2) & 3, t);
            attn_load(sb, Kg, Vg, 2 * pr + 3, (2 * pr + 3) & 3, t);
        }
#pragma unroll
        for (int sub = 0; sub < 2; ++sub) {
            int kt = 2 * pr + sub;
            uint32_t ksm = sb + (uint32_t)(kt & 3) * AST;
            uint32_t vsm = ksm + KST;

            float CS[8][4] = {};
#pragma unroll
            for (int ds = 0; ds < 2; ++ds)
#pragma unroll
                for (int ntp = 0; ntp < 4; ++ntp) {
                    uint32_t b0, b1, b2, b3;
                    LDSM4(b0, b1, b2, b3,
                          ksm + (uint32_t)(ntp * 16 + lr) * TPK + (uint32_t)((ds * 16 + kbo) * 2));
                    mma16(CS[2 * ntp], aq[ds], b0, b1);
                    mma16(CS[2 * ntp + 1], aq[ds], b2, b3);
                }

            float mt0 = -1e30f, mt1 = -1e30f;
#pragma unroll
            for (int nt = 0; nt < 8; ++nt) {
                mt0 = fmaxf(mt0, fmaxf(CS[nt][0], CS[nt][1]));
                mt1 = fmaxf(mt1, fmaxf(CS[nt][2], CS[nt][3]));
            }
            mt0 = fmaxf(mt0, __shfl_xor_sync(0xffffffffu, mt0, 1));
            mt0 = fmaxf(mt0, __shfl_xor_sync(0xffffffffu, mt0, 2));
            mt1 = fmaxf(mt1, __shfl_xor_sync(0xffffffffu, mt1, 1));
            mt1 = fmaxf(mt1, __shfl_xor_sync(0xffffffffu, mt1, 2));
            float mn0 = fmaxf(mo0, mt0), mn1 = fmaxf(mo1, mt1);
            float nm0 = -mn0 * L2E, nm1 = -mn1 * L2E;
            float fac0 = ex2f(fmaf(mo0, L2E, nm0));
            float fac1 = ex2f(fmaf(mo1, L2E, nm1));
            float s0 = 0.f, s1 = 0.f;
#pragma unroll
            for (int nt = 0; nt < 8; ++nt) {
                float e0 = ex2f(fmaf(CS[nt][0], L2E, nm0));
                float e1 = ex2f(fmaf(CS[nt][1], L2E, nm0));
                float e2 = ex2f(fmaf(CS[nt][2], L2E, nm1));
                float e3 = ex2f(fmaf(CS[nt][3], L2E, nm1));
                s0 += e0 + e1; s1 += e2 + e3;
                CS[nt][0] = e0; CS[nt][1] = e1; CS[nt][2] = e2; CS[nt][3] = e3;
            }
            s0 += __shfl_xor_sync(0xffffffffu, s0, 1);
            s0 += __shfl_xor_sync(0xffffffffu, s0, 2);
            s1 += __shfl_xor_sync(0xffffffffu, s1, 1);
            s1 += __shfl_xor_sync(0xffffffffu, s1, 2);
            l0 = l0 * fac0 + s0; l1 = l1 * fac1 + s1;
            mo0 = mn0; mo1 = mn1;
#pragma unroll
            for (int nt = 0; nt < 8; ++nt) {
                CO[nt][0] *= fac0; CO[nt][1] *= fac0;
                CO[nt][2] *= fac1; CO[nt][3] *= fac1;
            }

#pragma unroll
            for (int kc = 0; kc < 4; ++kc) {
                uint32_t ap[4];
                ap[0] = packh2(CS[2 * kc][0], CS[2 * kc][1]);
                ap[1] = packh2(CS[2 * kc][2], CS[2 * kc][3]);
                ap[2] = packh2(CS[2 * kc + 1][0], CS[2 * kc + 1][1]);
                ap[3] = packh2(CS[2 * kc + 1][2], CS[2 * kc + 1][3]);
#pragma unroll
                for (int ntp = 0; ntp < 4; ++ntp) {
                    uint32_t b0, b1, b2, b3;
                    LDSM4(b0, b1, b2, b3,
                          vsm + (uint32_t)((ntp * 16 + lr) * 144 + (kc * 16 + kbo) * 2));
                    mma16(CO[2 * ntp], ap, b0, b1);
                    mma16(CO[2 * ntp + 1], ap, b2, b3);
                }
            }
        }
    }

    __syncthreads();
    float* Ob = sm;  // [64][133]
    float li0 = 1.0f / l0, li1 = 1.0f / l1;
#pragma unroll
    for (int nt = 0; nt < 8; ++nt) {
        int d = nt * 8 + 2 * j;
        int q = q0w + r4;
        Ob[d * 133 + q] = CO[nt][0] * li0;
        Ob[(d + 1) * 133 + q] = CO[nt][1] * li0;
        Ob[d * 133 + q + 8] = CO[nt][2] * li1;
        Ob[(d + 1) * 133 + q + 8] = CO[nt][3] * li1;
    }
    __syncthreads();
#pragma unroll
    for (int i = 0; i < 32; ++i) {
        int q = t & 127, d = (t >> 7) + 2 * i;
        size_t addr = ((size_t)(n * 1024 + h * 64 + d)) * 1024 + q0g + q;
        float r = tokens[addr] + Ob[d * 133 + q];
        g_t2[addr] = r;
        Ob[d * 133 + q] = r;
    }
    __syncthreads();
#pragma unroll
    for (int i = 0; i < 32; ++i) {
        int d = t & 63, l = (t >> 6) + 4 * i;
        g_t2T[((size_t)(n * 1024 + q0g + l)) * 1024 + h * 64 + d] = __float2half(Ob[d * 133 + l]);
    }
}

// ---------------- launch ----------------
extern "C" void kernel_launch(void* const* d_in, const int* in_sizes, int n_in,
                              void* d_out, int out_size)
{
    (void)in_sizes; (void)n_in; (void)out_size;
    const float* tokens = (const float*)d_in[0];
    const float* p[24];
    for (int i = 0; i < 24; ++i) p[i] = (const float*)d_in[1 + i];

    cudaFuncSetAttribute(qkv_tc, cudaFuncAttributeMaxDynamicSharedMemorySize, GEMM_SMEM);
    cudaFuncSetAttribute(fconv_tc, cudaFuncAttributeMaxDynamicSharedMemorySize, FCONV_SMEM);
    cudaFuncSetAttribute(attn_tc, cudaFuncAttributeMaxDynamicSharedMemorySize, ATTN_SMEM);

    int prep_blocks = TRANS_BLOCKS + (1024 * 1024 + 8 * 256 * 128 + 8 * 256 + 1024 + 255) / 256;
    prep_kernel<<<prep_blocks, 256>>>(tokens,
        p[0], p[1], p[2], p[3], p[4], p[5],
        p[6], p[7], p[8], p[9], p[10], p[11],
        p[12], p[13], p[14], p[15], p[16], p[17],
        p[18], p[19], p[20], p[21], p[22], p[23]);

    qkv_tc<<<dim3(8, 2, 64), 256, GEMM_SMEM>>>();
    attn_tc<<<dim3(8, 16, 8), 256, ATTN_SMEM>>>(tokens);
    fconv_tc<<<dim3(4, 8, 8), 512, FCONV_SMEM>>>((float*)d_out);
}

// round 11
// speedup vs baseline: 1.0118x; 1.0118x over previous
#include <cuda_runtime.h>
#include <cuda_fp16.h>
#include <cstdint>
#include <math.h>

// ---------------- scratch ----------------
__device__ __half g_kbuf[8 * 16 * 1024 * 32];   // [n][h][l][d]
__device__ __half g_qbuf[8 * 16 * 1024 * 32];   // [n][h][l][d] (pre-scaled 1/32)
__device__ __half g_vbuf[8 * 1024 * 1024];      // [n][c][l]
__device__ float  g_t2 [8 * 1024 * 1024];       // [n][c][l] fp32 residual
__device__ __half g_t2b[8 * 1024 * 1024];       // blocked+swizzled [n][kc16][l][64h]
__device__ __half g_tokT[8 * 1024 * 1024];      // [n][l][c]
__device__ __half g_wg[8 * 256 * 128];          // [g][r][k]
__device__ float  g_bg[8 * 256];
__device__ __half g_wfb[1024 * 1024];           // blocked+swizzled [cb8][kc16][m128][64h]
__device__ float  g_bf[1024];

// ---------------- helpers ----------------
__device__ __forceinline__ uint32_t smem_u32(const void* p) {
    uint32_t a;
    asm("{ .reg .u64 t; cvta.to.shared.u64 t, %1; cvt.u32.u64 %0, t; }" : "=r"(a) : "l"(p));
    return a;
}
#define CPA(dst, src) asm volatile("cp.async.cg.shared.global [%0], [%1], 16;" :: "r"(dst), "l"(__cvta_generic_to_global(src)))
#define CPC()  asm volatile("cp.async.commit_group;" ::: "memory")
#define CPW0() asm volatile("cp.async.wait_group 0;" ::: "memory")
#define CPW1() asm volatile("cp.async.wait_group 1;" ::: "memory")
#define LDSM4(r0, r1, r2, r3, a) \
    asm volatile("ldmatrix.sync.aligned.m8n8.x4.shared.b16 {%0,%1,%2,%3}, [%4];" \
        : "=r"(r0), "=r"(r1), "=r"(r2), "=r"(r3) : "r"(a))

#define MBAR_INIT(a, c) asm volatile("mbarrier.init.shared.b64 [%0], %1;" :: "r"(a), "r"(c) : "memory")
#define MBAR_EXPECT(a, bytes) \
    asm volatile("mbarrier.arrive.expect_tx.shared.b64 _, [%0], %1;" :: "r"(a), "r"(bytes) : "memory")
#define CPBULK(dstS, srcG, bytes, mbar) \
    asm volatile("cp.async.bulk.shared::cta.global.mbarrier::complete_tx::bytes [%0], [%1], %2, [%3];" \
        :: "r"(dstS), "l"(__cvta_generic_to_global(srcG)), "r"(bytes), "r"(mbar) : "memory")
#define MBAR_WAIT(mbar_addr, parity) do { \
    uint32_t _m = (mbar_addr), _p = (parity), _d; \
    asm volatile("{\n\t.reg .pred p;\n\t" \
        "mbarrier.try_wait.parity.acquire.cta.shared::cta.b64 p, [%1], %2;\n\t" \
        "selp.b32 %0, 1, 0, p;\n\t}" : "=r"(_d) : "r"(_m), "r"(_p) : "memory"); \
    if (!_d) { \
        asm volatile("{\n\t.reg .pred P1;\n\t" \
            "WL_%=:\n\t" \
            "mbarrier.try_wait.parity.acquire.cta.shared::cta.b64 P1, [%0], %1, 0x989680;\n\t" \
            "@P1 bra.uni WD_%=;\n\t" \
            "bra.uni WL_%=;\n\t" \
            "WD_%=:\n\t}" :: "r"(_m), "r"(_p) : "memory"); \
    } \
} while (0)

__device__ __forceinline__ void mma16(float* d, const uint32_t* a, uint32_t b0, uint32_t b1) {
    asm volatile(
        "mma.sync.aligned.m16n8k16.row.col.f32.f16.f16.f32 "
        "{%0,%1,%2,%3}, {%4,%5,%6,%7}, {%8,%9}, {%0,%1,%2,%3};"
        : "+f"(d[0]), "+f"(d[1]), "+f"(d[2]), "+f"(d[3])
        : "r"(a[0]), "r"(a[1]), "r"(a[2]), "r"(a[3]), "r"(b0), "r"(b1));
}
__device__ __forceinline__ uint32_t packh2(float a, float b) {
    __half2 h = __floats2half2_rn(a, b);
    return *(uint32_t*)&h;
}
__device__ __forceinline__ float ex2f(float x) {
    float r;
    asm("ex2.approx.f32 %0, %1;" : "=f"(r) : "f"(x));
    return r;
}
#define L2E 1.4426950408889634f

// ---------------- fused prep + tokens transpose ----------------
#define TRANS_BLOCKS 8192
__global__ __launch_bounds__(256) void prep_kernel(
    const float* __restrict__ tokens,
    const float* __restrict__ kw, const float* __restrict__ kb, const float* __restrict__ kga,
    const float* __restrict__ kbe, const float* __restrict__ km, const float* __restrict__ kv,
    const float* __restrict__ qw, const float* __restrict__ qb, const float* __restrict__ qga,
    const float* __restrict__ qbe, const float* __restrict__ qm, const float* __restrict__ qv,
    const float* __restrict__ vw, const float* __restrict__ vb, const float* __restrict__ vga,
    const float* __restrict__ vbe, const float* __restrict__ vm, const float* __restrict__ vv,
    const float* __restrict__ fw, const float* __restrict__ fb, const float* __restrict__ fga,
    const float* __restrict__ fbe, const float* __restrict__ fm, const float* __restrict__ fv)
{
    __shared__ float tile[32][33];
    int t = threadIdx.x;
    if (blockIdx.x < TRANS_BLOCKS) {
        int bid = blockIdx.x;
        int l0 = (bid & 31) * 32, c0 = ((bid >> 5) & 31) * 32, n = bid >> 10;
#pragma unroll
        for (int i = 0; i < 4; ++i) {
            int idx = i * 256 + t;
            int r = idx >> 5, col = idx & 31;
            tile[r][col] = tokens[((size_t)(n * 1024 + c0 + r)) * 1024 + l0 + col];
        }
        __syncthreads();
#pragma unroll
        for (int i = 0; i < 4; ++i) {
            int idx = i * 256 + t;
            int r = idx >> 5, col = idx & 31;
            g_tokT[((size_t)(n * 1024 + l0 + r)) * 1024 + c0 + col] = __float2half(tile[col][r]);
        }
        return;
    }
    int id = (blockIdx.x - TRANS_BLOCKS) * 256 + t;
    if (id < 1024 * 1024) {
        int k = id & 1023, c = id >> 10;
        float inv = fga[c] * rsqrtf(fv[c] + 1e-5f);
        int cb = c >> 7, m = c & 127, kc = k >> 6, ch = (k >> 3) & 7, w = k & 7;
        size_t dst = ((size_t)((cb * 16 + kc) * 128 + m)) * 64 + ((ch ^ (m & 7)) << 3) + w;
        g_wfb[dst] = __float2half(fw[id] * inv);
        return;
    }
    int id2 = id - 1024 * 1024;
    if (id2 < 8 * 256 * 128) {
        int k = id2 & 127;
        int r = (id2 >> 7) & 255;
        int g = id2 >> 15;
        float w;
        if (r < 64) {
            int c = g * 64 + r;
            float inv = kga[c] * rsqrtf(kv[c] + 1e-5f);
            w = kw[c * 128 + k] * inv;
        } else if (r < 128) {
            int c = g * 64 + (r - 64);
            float inv = qga[c] * rsqrtf(qv[c] + 1e-5f);
            w = qw[c * 128 + k] * inv * 0.03125f;
        } else {
            int c = g * 128 + (r - 128);
            float inv = vga[c] * rsqrtf(vv[c] + 1e-5f);
            w = vw[c * 128 + k] * inv;
        }
        g_wg[id2] = __float2half(w);
        return;
    }
    int id3 = id2 - 8 * 256 * 128;
    if (id3 < 8 * 256) {
        int g = id3 >> 8, r = id3 & 255;
        float bias;
        if (r < 64) {
            int c = g * 64 + r;
            float inv = kga[c] * rsqrtf(kv[c] + 1e-5f);
            bias = kb[c] * inv + kbe[c] - km[c] * inv;
        } else if (r < 128) {
            int c = g * 64 + (r - 64);
            float inv = qga[c] * rsqrtf(qv[c] + 1e-5f);
            bias = (qb[c] * inv + qbe[c] - qm[c] * inv) * 0.03125f;
        } else {
            int c = g * 128 + (r - 128);
            float inv = vga[c] * rsqrtf(vv[c] + 1e-5f);
            bias = vb[c] * inv + vbe[c] - vm[c] * inv;
        }
        g_bg[id3] = bias;
        return;
    }
    int c = id3 - 8 * 256;
    if (c < 1024) {
        float inv = fga[c] * rsqrtf(fv[c] + 1e-5f);
        g_bf[c] = fb[c] * inv + fbe[c] - fm[c] * inv;
    }
}

// ---------------- GEMM pieces (fp16, ldmatrix, K-chunk 64, padded pitch) ----------------
#define TP64 144u
#define GTILE 18432u
#define GSTG  36864u
#define GEMM_SMEM 110592
__device__ __forceinline__ void load_tile64(uint32_t dst, const __half* src, int stride_h, int t)
{
#pragma unroll
    for (int i = 0; i < 4; ++i) {
        int idx = i * 256 + t;
        int row = idx >> 3, c16 = idx & 7;
        CPA(dst + (uint32_t)row * TP64 + (uint32_t)c16 * 16u, src + (size_t)row * stride_h + c16 * 8);
    }
}

__device__ __forceinline__ void wgemm64(uint32_t As, uint32_t Bs, float C[4][4][4], int lane,
                                        int m0, int n0)
{
    int lr = (lane & 7) + ((lane >> 3) & 1) * 8;
    int akb = ((lane >> 4) & 1) * 8;
    int br = (lane & 7) + ((lane >> 4) & 1) * 8;
    int bkb = ((lane >> 3) & 1) * 8;
#pragma unroll
    for (int ks = 0; ks < 4; ++ks) {
        uint32_t a[4][4];
#pragma unroll
        for (int mi = 0; mi < 4; ++mi)
            LDSM4(a[mi][0], a[mi][1], a[mi][2], a[mi][3],
                  As + (uint32_t)(m0 + mi * 16 + lr) * TP64 + (uint32_t)((ks * 16 + akb) * 2));
#pragma unroll
        for (int np = 0; np < 2; ++np) {
            uint32_t b0, b1, b2, b3;
            LDSM4(b0, b1, b2, b3,
                  Bs + (uint32_t)(n0 + np * 16 + br) * TP64 + (uint32_t)((ks * 16 + bkb) * 2));
#pragma unroll
            for (int mi = 0; mi < 4; ++mi) {
                mma16(C[mi][np * 2], a[mi], b0, b1);
                mma16(C[mi][np * 2 + 1], a[mi], b2, b3);
            }
        }
    }
}

// ---------------- qkv conv GEMM (unchanged) ----------------
__global__ __launch_bounds__(256, 2) void qkv_tc()
{
    extern __shared__ float sm[];
    uint32_t sb = smem_u32(sm);
    int t = threadIdx.x, wid = t >> 5, lane = t & 31;
    int lt = blockIdx.x, rb = blockIdx.y, ng = blockIdx.z;
    int n = ng >> 3, g = ng & 7;
    int l0 = lt * 128;
    int m0 = (wid & 1) * 64, n0 = (wid >> 1) * 32;
    const __half* Ag = g_wg + (size_t)(g * 256 + rb * 128) * 128;
    const __half* Bg = g_tokT + ((size_t)(n * 1024 + l0)) * 1024 + g * 128;

    float C[4][4][4] = {};
    load_tile64(sb, Ag, 128, t);
    load_tile64(sb + GTILE, Bg, 1024, t);
    CPC();
    load_tile64(sb + GSTG, Ag + 64, 128, t);
    load_tile64(sb + GSTG + GTILE, Bg + 64, 1024, t);
    CPC();
    for (int c = 0; c < 2; ++c) {
        if (c == 0) CPW1(); else CPW0();
        __syncthreads();
        uint32_t As = sb + (uint32_t)c * GSTG;
        wgemm64(As, As + GTILE, C, lane, m0, n0);
    }
    __syncthreads();

    float* Sb = sm;  // [128][33]
    int r4 = lane >> 2, j = lane & 3;
    for (int ch = 0; ch < 4; ++ch) {
        if ((wid >> 1) == ch) {
#pragma unroll
            for (int mi = 0; mi < 4; ++mi)
#pragma unroll
                for (int ni = 0; ni < 4; ++ni) {
                    int m = m0 + mi * 16 + r4;
                    int q = ni * 8 + 2 * j;
                    Sb[m * 33 + q] = C[mi][ni][0];
                    Sb[m * 33 + q + 1] = C[mi][ni][1];
                    Sb[(m + 8) * 33 + q] = C[mi][ni][2];
                    Sb[(m + 8) * 33 + q + 1] = C[mi][ni][3];
                }
        }
        __syncthreads();
        if (rb == 0) {
#pragma unroll
            for (int i = 0; i < 8; ++i) {
                int m = t & 63, l = (t >> 6) + 4 * i;
                int h = 2 * g + (m >> 5), d = m & 31;
                size_t base = (((size_t)(n * 16 + h)) * 1024 + l0 + ch * 32 + l) * 32 + d;
                g_kbuf[base] = __float2half(Sb[m * 33 + l] + g_bg[g * 256 + m]);
                g_qbuf[base] = __float2half(Sb[(m + 64) * 33 + l] + g_bg[g * 256 + 64 + m]);
            }
        } else {
#pragma unroll
            for (int i = 0; i < 16; ++i) {
                int l = t & 31, m = (t >> 5) + 8 * i;
                g_vbuf[((size_t)(n * 1024 + g * 128 + m)) * 1024 + l0 + ch * 32 + l] =
                    __float2half(Sb[m * 33 + l] + g_bg[g * 256 + 128 + m]);
            }
        }
        __syncthreads();
    }
}

// ---------------- ff conv: bulk-copy (UBLKCP) 4-stage pipeline, 512 thr, 128x256 ----------------
#define FA 16384u
#define FB 32768u
#define FSTG 49152u
#define FCONV_SMEM 196608
#define SWA(row, ch) (((uint32_t)(row) << 7) + (uint32_t)(((ch) ^ ((row) & 7)) << 4))

__global__ __launch_bounds__(512, 1) void fconv_tc(float* __restrict__ out)
{
    extern __shared__ float sm[];
    uint32_t sb = smem_u32(sm);
    __shared__ __align__(8) uint64_t s_mbar[4];
    int t = threadIdx.x, wid = t >> 5, lane = t & 31;
    int lt = blockIdx.x, cb = blockIdx.y, n = blockIdx.z;
    int l0 = lt * 256;
    int m0 = (wid & 1) * 64, n0 = (wid >> 1) * 32;
    const __half* Ag = g_wfb + (size_t)(cb * 16) * 128 * 64;      // + c*8192
    const __half* Bg = g_t2b + (size_t)(n * 16) * 1024 * 64;      // + (c*1024 + l0)*64

    if (t == 0) {
#pragma unroll
        for (int s = 0; s < 4; ++s) MBAR_INIT(smem_u32(&s_mbar[s]), 1);
    }
    __syncthreads();
    if (t == 0) {
#pragma unroll
        for (int c = 0; c < 3; ++c) {
            uint32_t mb = smem_u32(&s_mbar[c]);
            MBAR_EXPECT(mb, FSTG);
            CPBULK(sb + (uint32_t)c * FSTG, Ag + (size_t)c * 8192, FA, mb);
            CPBULK(sb + (uint32_t)c * FSTG + FA, Bg + ((size_t)c * 1024 + l0) * 64, FB, mb);
        }
    }

    float C[4][4][4] = {};
    int lr = (lane & 7) + ((lane >> 3) & 1) * 8;
    int akb8 = (lane >> 4) & 1;
    int br = (lane & 7) + ((lane >> 4) & 1) * 8;
    int bkb8 = (lane >> 3) & 1;

    for (int c = 0; c < 16; ++c) {
        MBAR_WAIT(smem_u32(&s_mbar[c & 3]), (c >> 2) & 1);
        __syncthreads();
        if (t == 0 && c + 3 < 16) {
            int nc = c + 3;
            uint32_t mb = smem_u32(&s_mbar[nc & 3]);
            MBAR_EXPECT(mb, FSTG);
            CPBULK(sb + (uint32_t)(nc & 3) * FSTG, Ag + (size_t)nc * 8192, FA, mb);
            CPBULK(sb + (uint32_t)(nc & 3) * FSTG + FA, Bg + ((size_t)nc * 1024 + l0) * 64, FB, mb);
        }
        uint32_t As = sb + (uint32_t)(c & 3) * FSTG;
        uint32_t Bs = As + FA;
#pragma unroll
        for (int ks = 0; ks < 4; ++ks) {
            uint32_t a[4][4];
#pragma unroll
            for (int mi = 0; mi < 4; ++mi) {
                int row = m0 + mi * 16 + lr;
                LDSM4(a[mi][0], a[mi][1], a[mi][2], a[mi][3], As + SWA(row, ks * 2 + akb8));
            }
#pragma unroll
            for (int np = 0; np < 2; ++np) {
                int row = n0 + np * 16 + br;
                uint32_t b0, b1, b2, b3;
                LDSM4(b0, b1, b2, b3, Bs + SWA(row, ks * 2 + bkb8));
#pragma unroll
                for (int mi = 0; mi < 4; ++mi) {
                    mma16(C[mi][np * 2], a[mi], b0, b1);
                    mma16(C[mi][np * 2 + 1], a[mi], b2, b3);
                }
            }
        }
    }
    __syncthreads();

    float* Sb = sm;   // [128][33] fp32
    int r4 = lane >> 2, j = lane & 3;
    for (int ch = 0; ch < 8; ++ch) {
        if ((wid >> 1) == ch) {
#pragma unroll
            for (int mi = 0; mi < 4; ++mi)
#pragma unroll
                for (int ni = 0; ni < 4; ++ni) {
                    int m = m0 + mi * 16 + r4;
                    int q = ni * 8 + 2 * j;
                    Sb[m * 33 + q] = C[mi][ni][0];
                    Sb[m * 33 + q + 1] = C[mi][ni][1];
                    Sb[(m + 8) * 33 + q] = C[mi][ni][2];
                    Sb[(m + 8) * 33 + q + 1] = C[mi][ni][3];
                }
        }
        __syncthreads();
#pragma unroll
        for (int i = 0; i < 8; ++i) {
            int l = t & 31, m = (t >> 5) + 16 * i;
            size_t addr = ((size_t)(n * 1024 + cb * 128 + m)) * 1024 + l0 + ch * 32 + l;
            out[addr] = Sb[m * 33 + l] + g_bf[cb * 128 + m] + g_t2[addr];
        }
        __syncthreads();
    }
}

// ---------------- flash attention: 4-stage, paired tiles (R9) ----------------
#define TPK 80u
#define KST 5120u
#define AST 14336u
#define ATTN_SMEM 57344

__device__ __forceinline__ void attn_load(uint32_t sb, const __half* Kg, const __half* Vg,
                                          int kt, int st, int t)
{
    uint32_t base = sb + (uint32_t)st * AST;
    int k0 = kt * 64;
    int row = t >> 2, c16 = t & 3;
    CPA(base + (uint32_t)row * TPK + (uint32_t)c16 * 16u, Kg + (size_t)(k0 + row) * 32 + c16 * 8);
#pragma unroll
    for (int i = 0; i < 2; ++i) {
        int idx = i * 256 + t;
        int vr = idx >> 3, vc = idx & 7;
        CPA(base + KST + (uint32_t)(vr * 144 + vc * 16), Vg + (size_t)vr * 1024 + k0 + vc * 8);
    }
    CPC();
}

__global__ __launch_bounds__(256, 2) void attn_tc(const float* __restrict__ tokens)
{
    extern __shared__ float sm[];
    uint32_t sb = smem_u32(sm);

    int t = threadIdx.x, wid = t >> 5, lane = t & 31;
    int r4 = lane >> 2, j = lane & 3;
    int qt = blockIdx.x, h = blockIdx.y, n = blockIdx.z;
    int q0g = qt * 128, q0w = wid * 16;
    const __half* Kg = g_kbuf + ((size_t)(n * 16 + h)) * 1024 * 32;
    const __half* Qg = g_qbuf + ((size_t)(n * 16 + h)) * 1024 * 32;
    const __half* Vg = g_vbuf + ((size_t)(n * 1024 + h * 64)) * 1024;

    uint32_t aq[2][4];
#pragma unroll
    for (int ds = 0; ds < 2; ++ds) {
        const __half* qb = Qg + (size_t)(q0g + q0w + r4) * 32 + ds * 16 + 2 * j;
        aq[ds][0] = *(const uint32_t*)qb;
        aq[ds][1] = *(const uint32_t*)(qb + 8 * 32);
        aq[ds][2] = *(const uint32_t*)(qb + 8);
        aq[ds][3] = *(const uint32_t*)(qb + 8 * 32 + 8);
    }

    attn_load(sb, Kg, Vg, 0, 0, t);
    attn_load(sb, Kg, Vg, 1, 1, t);

    float CO[8][4] = {};
    float mo0 = -1e30f, mo1 = -1e30f, l0 = 0.f, l1 = 0.f;
    int lr = (lane & 7) + ((lane >> 4) & 1) * 8;
    int kbo = ((lane >> 3) & 1) * 8;

    for (int pr = 0; pr < 8; ++pr) {
        CPW0();
        __syncthreads();
        if (pr < 7) {
            attn_load(sb, Kg, Vg, 2 * pr + 2, (2 * pr + 2) & 3, t);
            attn_load(sb, Kg, Vg, 2 * pr + 3, (2 * pr + 3) & 3, t);
        }
#pragma unroll
        for (int sub = 0; sub < 2; ++sub) {
            int kt = 2 * pr + sub;
            uint32_t ksm = sb + (uint32_t)(kt & 3) * AST;
            uint32_t vsm = ksm + KST;

            float CS[8][4] = {};
#pragma unroll
            for (int ds = 0; ds < 2; ++ds)
#pragma unroll
                for (int ntp = 0; ntp < 4; ++ntp) {
                    uint32_t b0, b1, b2, b3;
                    LDSM4(b0, b1, b2, b3,
                          ksm + (uint32_t)(ntp * 16 + lr) * TPK + (uint32_t)((ds * 16 + kbo) * 2));
                    mma16(CS[2 * ntp], aq[ds], b0, b1);
                    mma16(CS[2 * ntp + 1], aq[ds], b2, b3);
                }

            float mt0 = -1e30f, mt1 = -1e30f;
#pragma unroll
            for (int nt = 0; nt < 8; ++nt) {
                mt0 = fmaxf(mt0, fmaxf(CS[nt][0], CS[nt][1]));
                mt1 = fmaxf(mt1, fmaxf(CS[nt][2], CS[nt][3]));
            }
            mt0 = fmaxf(mt0, __shfl_xor_sync(0xffffffffu, mt0, 1));
            mt0 = fmaxf(mt0, __shfl_xor_sync(0xffffffffu, mt0, 2));
            mt1 = fmaxf(mt1, __shfl_xor_sync(0xffffffffu, mt1, 1));
            mt1 = fmaxf(mt1, __shfl_xor_sync(0xffffffffu, mt1, 2));
            float mn0 = fmaxf(mo0, mt0), mn1 = fmaxf(mo1, mt1);
            float nm0 = -mn0 * L2E, nm1 = -mn1 * L2E;
            float fac0 = ex2f(fmaf(mo0, L2E, nm0));
            float fac1 = ex2f(fmaf(mo1, L2E, nm1));
            float s0 = 0.f, s1 = 0.f;
#pragma unroll
            for (int nt = 0; nt < 8; ++nt) {
                float e0 = ex2f(fmaf(CS[nt][0], L2E, nm0));
                float e1 = ex2f(fmaf(CS[nt][1], L2E, nm0));
                float e2 = ex2f(fmaf(CS[nt][2], L2E, nm1));
                float e3 = ex2f(fmaf(CS[nt][3], L2E, nm1));
                s0 += e0 + e1; s1 += e2 + e3;
                CS[nt][0] = e0; CS[nt][1] = e1; CS[nt][2] = e2; CS[nt][3] = e3;
            }
            s0 += __shfl_xor_sync(0xffffffffu, s0, 1);
            s0 += __shfl_xor_sync(0xffffffffu, s0, 2);
            s1 += __shfl_xor_sync(0xffffffffu, s1, 1);
            s1 += __shfl_xor_sync(0xffffffffu, s1, 2);
            l0 = l0 * fac0 + s0; l1 = l1 * fac1 + s1;
            mo0 = mn0; mo1 = mn1;
#pragma unroll
            for (int nt = 0; nt < 8; ++nt) {
                CO[nt][0] *= fac0; CO[nt][1] *= fac0;
                CO[nt][2] *= fac1; CO[nt][3] *= fac1;
            }

#pragma unroll
            for (int kc = 0; kc < 4; ++kc) {
                uint32_t ap[4];
                ap[0] = packh2(CS[2 * kc][0], CS[2 * kc][1]);
                ap[1] = packh2(CS[2 * kc][2], CS[2 * kc][3]);
                ap[2] = packh2(CS[2 * kc + 1][0], CS[2 * kc + 1][1]);
                ap[3] = packh2(CS[2 * kc + 1][2], CS[2 * kc + 1][3]);
#pragma unroll
                for (int ntp = 0; ntp < 4; ++ntp) {
                    uint32_t b0, b1, b2, b3;
                    LDSM4(b0, b1, b2, b3,
                          vsm + (uint32_t)((ntp * 16 + lr) * 144 + (kc * 16 + kbo) * 2));
                    mma16(CO[2 * ntp], ap, b0, b1);
                    mma16(CO[2 * ntp + 1], ap, b2, b3);
                }
            }
        }
    }

    __syncthreads();
    float* Ob = sm;  // [64][133]
    float li0 = 1.0f / l0, li1 = 1.0f / l1;
#pragma unroll
    for (int nt = 0; nt < 8; ++nt) {
        int d = nt * 8 + 2 * j;
        int q = q0w + r4;
        Ob[d * 133 + q] = CO[nt][0] * li0;
        Ob[(d + 1) * 133 + q] = CO[nt][1] * li0;
        Ob[d * 133 + q + 8] = CO[nt][2] * li1;
        Ob[(d + 1) * 133 + q + 8] = CO[nt][3] * li1;
    }
    __syncthreads();
#pragma unroll
    for (int i = 0; i < 32; ++i) {
        int q = t & 127, d = (t >> 7) + 2 * i;
        size_t addr = ((size_t)(n * 1024 + h * 64 + d)) * 1024 + q0g + q;
        float r = tokens[addr] + Ob[d * 133 + q];
        g_t2[addr] = r;
        Ob[d * 133 + q] = r;
    }
    __syncthreads();
    // blocked + pre-swizzled t2 transpose for fconv bulk loads
#pragma unroll
    for (int i = 0; i < 32; ++i) {
        int d = t & 63, l = (t >> 6) + 4 * i;
        int lg = q0g + l;
        size_t dst = ((size_t)(n * 16 + h) * 1024 + lg) * 64 + (((d >> 3) ^ (lg & 7)) << 3) + (d & 7);
        g_t2b[dst] = __float2half(Ob[d * 133 + l]);
    }
}

// ---------------- launch ----------------
extern "C" void kernel_launch(void* const* d_in, const int* in_sizes, int n_in,
                              void* d_out, int out_size)
{
    (void)in_sizes; (void)n_in; (void)out_size;
    const float* tokens = (const float*)d_in[0];
    const float* p[24];
    for (int i = 0; i < 24; ++i) p[i] = (const float*)d_in[1 + i];

    cudaFuncSetAttribute(qkv_tc, cudaFuncAttributeMaxDynamicSharedMemorySize, GEMM_SMEM);
    cudaFuncSetAttribute(fconv_tc, cudaFuncAttributeMaxDynamicSharedMemorySize, FCONV_SMEM);
    cudaFuncSetAttribute(attn_tc, cudaFuncAttributeMaxDynamicSharedMemorySize, ATTN_SMEM);

    int prep_blocks = TRANS_BLOCKS + (1024 * 1024 + 8 * 256 * 128 + 8 * 256 + 1024 + 255) / 256;
    prep_kernel<<<prep_blocks, 256>>>(tokens,
        p[0], p[1], p[2], p[3], p[4], p[5],
        p[6], p[7], p[8], p[9], p[10], p[11],
        p[12], p[13], p[14], p[15], p[16], p[17],
        p[18], p[19], p[20], p[21], p[22], p[23]);

    qkv_tc<<<dim3(8, 2, 64), 256, GEMM_SMEM>>>();
    attn_tc<<<dim3(8, 16, 8), 256, ATTN_SMEM>>>(tokens);
    fconv_tc<<<dim3(4, 8, 8), 512, FCONV_SMEM>>>((float*)d_out);
}

// round 12
// speedup vs baseline: 1.1241x; 1.1111x over previous
#include <cuda_runtime.h>
#include <cuda_fp16.h>
#include <cstdint>
#include <math.h>

// ---------------- scratch ----------------
__device__ __half g_kbuf[8 * 16 * 1024 * 32];   // [n][h][l][d]
__device__ __half g_qbuf[8 * 16 * 1024 * 32];   // [n][h][l][d] (pre-scaled 1/32)
__device__ __half g_vbuf[8 * 1024 * 1024];      // [n][c][l]
__device__ float  g_t2 [8 * 1024 * 1024];       // [n][c][l] fp32 residual
__device__ __half g_t2b[8 * 1024 * 1024];       // blocked+swizzled [n][kc16][l][64h]
__device__ __half g_tokT[8 * 1024 * 1024];      // [n][l][c]
__device__ __half g_wg[8 * 256 * 128];          // [g][r][k]
__device__ float  g_bg[8 * 256];
__device__ __half g_wfb[1024 * 1024];           // blocked+swizzled [cb8][kc16][m128][64h]
__device__ float  g_bf[1024];

// ---------------- helpers ----------------
__device__ __forceinline__ uint32_t smem_u32(const void* p) {
    uint32_t a;
    asm("{ .reg .u64 t; cvta.to.shared.u64 t, %1; cvt.u32.u64 %0, t; }" : "=r"(a) : "l"(p));
    return a;
}
#define CPA(dst, src) asm volatile("cp.async.cg.shared.global [%0], [%1], 16;" :: "r"(dst), "l"(__cvta_generic_to_global(src)))
#define CPC()  asm volatile("cp.async.commit_group;" ::: "memory")
#define CPW0() asm volatile("cp.async.wait_group 0;" ::: "memory")
#define CPW1() asm volatile("cp.async.wait_group 1;" ::: "memory")
#define LDSM4(r0, r1, r2, r3, a) \
    asm volatile("ldmatrix.sync.aligned.m8n8.x4.shared.b16 {%0,%1,%2,%3}, [%4];" \
        : "=r"(r0), "=r"(r1), "=r"(r2), "=r"(r3) : "r"(a))

#define MBAR_INIT(a, c) asm volatile("mbarrier.init.shared.b64 [%0], %1;" :: "r"(a), "r"(c) : "memory")
#define MBAR_EXPECT(a, bytes) \
    asm volatile("mbarrier.arrive.expect_tx.shared.b64 _, [%0], %1;" :: "r"(a), "r"(bytes) : "memory")
#define CPBULK(dstS, srcG, bytes, mbar) \
    asm volatile("cp.async.bulk.shared::cta.global.mbarrier::complete_tx::bytes [%0], [%1], %2, [%3];" \
        :: "r"(dstS), "l"(__cvta_generic_to_global(srcG)), "r"(bytes), "r"(mbar) : "memory")
#define MBAR_WAIT(mbar_addr, parity) do { \
    uint32_t _m = (mbar_addr), _p = (parity), _d; \
    asm volatile("{\n\t.reg .pred p;\n\t" \
        "mbarrier.try_wait.parity.acquire.cta.shared::cta.b64 p, [%1], %2;\n\t" \
        "selp.b32 %0, 1, 0, p;\n\t}" : "=r"(_d) : "r"(_m), "r"(_p) : "memory"); \
    if (!_d) { \
        asm volatile("{\n\t.reg .pred P1;\n\t" \
            "WL_%=:\n\t" \
            "mbarrier.try_wait.parity.acquire.cta.shared::cta.b64 P1, [%0], %1, 0x989680;\n\t" \
            "@P1 bra.uni WD_%=;\n\t" \
            "bra.uni WL_%=;\n\t" \
            "WD_%=:\n\t}" :: "r"(_m), "r"(_p) : "memory"); \
    } \
} while (0)

__device__ __forceinline__ void mma16(float* d, const uint32_t* a, uint32_t b0, uint32_t b1) {
    asm volatile(
        "mma.sync.aligned.m16n8k16.row.col.f32.f16.f16.f32 "
        "{%0,%1,%2,%3}, {%4,%5,%6,%7}, {%8,%9}, {%0,%1,%2,%3};"
        : "+f"(d[0]), "+f"(d[1]), "+f"(d[2]), "+f"(d[3])
        : "r"(a[0]), "r"(a[1]), "r"(a[2]), "r"(a[3]), "r"(b0), "r"(b1));
}
__device__ __forceinline__ uint32_t packh2(float a, float b) {
    __half2 h = __floats2half2_rn(a, b);
    return *(uint32_t*)&h;
}
__device__ __forceinline__ float ex2f(float x) {
    float r;
    asm("ex2.approx.f32 %0, %1;" : "=f"(r) : "f"(x));
    return r;
}
#define L2E 1.4426950408889634f

// ---------------- fused prep + tokens transpose ----------------
#define TRANS_BLOCKS 8192
__global__ __launch_bounds__(256) void prep_kernel(
    const float* __restrict__ tokens,
    const float* __restrict__ kw, const float* __restrict__ kb, const float* __restrict__ kga,
    const float* __restrict__ kbe, const float* __restrict__ km, const float* __restrict__ kv,
    const float* __restrict__ qw, const float* __restrict__ qb, const float* __restrict__ qga,
    const float* __restrict__ qbe, const float* __restrict__ qm, const float* __restrict__ qv,
    const float* __restrict__ vw, const float* __restrict__ vb, const float* __restrict__ vga,
    const float* __restrict__ vbe, const float* __restrict__ vm, const float* __restrict__ vv,
    const float* __restrict__ fw, const float* __restrict__ fb, const float* __restrict__ fga,
    const float* __restrict__ fbe, const float* __restrict__ fm, const float* __restrict__ fv)
{
    __shared__ float tile[32][33];
    int t = threadIdx.x;
    if (blockIdx.x < TRANS_BLOCKS) {
        int bid = blockIdx.x;
        int l0 = (bid & 31) * 32, c0 = ((bid >> 5) & 31) * 32, n = bid >> 10;
#pragma unroll
        for (int i = 0; i < 4; ++i) {
            int idx = i * 256 + t;
            int r = idx >> 5, col = idx & 31;
            tile[r][col] = tokens[((size_t)(n * 1024 + c0 + r)) * 1024 + l0 + col];
        }
        __syncthreads();
#pragma unroll
        for (int i = 0; i < 4; ++i) {
            int idx = i * 256 + t;
            int r = idx >> 5, col = idx & 31;
            g_tokT[((size_t)(n * 1024 + l0 + r)) * 1024 + c0 + col] = __float2half(tile[col][r]);
        }
        return;
    }
    int id = (blockIdx.x - TRANS_BLOCKS) * 256 + t;
    if (id < 1024 * 1024) {
        int k = id & 1023, c = id >> 10;
        float inv = fga[c] * rsqrtf(fv[c] + 1e-5f);
        int cb = c >> 7, m = c & 127, kc = k >> 6, ch = (k >> 3) & 7, w = k & 7;
        size_t dst = ((size_t)((cb * 16 + kc) * 128 + m)) * 64 + ((ch ^ (m & 7)) << 3) + w;
        g_wfb[dst] = __float2half(fw[id] * inv);
        return;
    }
    int id2 = id - 1024 * 1024;
    if (id2 < 8 * 256 * 128) {
        int k = id2 & 127;
        int r = (id2 >> 7) & 255;
        int g = id2 >> 15;
        float w;
        if (r < 64) {
            int c = g * 64 + r;
            float inv = kga[c] * rsqrtf(kv[c] + 1e-5f);
            w = kw[c * 128 + k] * inv;
        } else if (r < 128) {
            int c = g * 64 + (r - 64);
            float inv = qga[c] * rsqrtf(qv[c] + 1e-5f);
            w = qw[c * 128 + k] * inv * 0.03125f;
        } else {
            int c = g * 128 + (r - 128);
            float inv = vga[c] * rsqrtf(vv[c] + 1e-5f);
            w = vw[c * 128 + k] * inv;
        }
        g_wg[id2] = __float2half(w);
        return;
    }
    int id3 = id2 - 8 * 256 * 128;
    if (id3 < 8 * 256) {
        int g = id3 >> 8, r = id3 & 255;
        float bias;
        if (r < 64) {
            int c = g * 64 + r;
            float inv = kga[c] * rsqrtf(kv[c] + 1e-5f);
            bias = kb[c] * inv + kbe[c] - km[c] * inv;
        } else if (r < 128) {
            int c = g * 64 + (r - 64);
            float inv = qga[c] * rsqrtf(qv[c] + 1e-5f);
            bias = (qb[c] * inv + qbe[c] - qm[c] * inv) * 0.03125f;
        } else {
            int c = g * 128 + (r - 128);
            float inv = vga[c] * rsqrtf(vv[c] + 1e-5f);
            bias = vb[c] * inv + vbe[c] - vm[c] * inv;
        }
        g_bg[id3] = bias;
        return;
    }
    int c = id3 - 8 * 256;
    if (c < 1024) {
        float inv = fga[c] * rsqrtf(fv[c] + 1e-5f);
        g_bf[c] = fb[c] * inv + fbe[c] - fm[c] * inv;
    }
}

// ---------------- GEMM pieces (fp16, ldmatrix, K-chunk 64, padded pitch) ----------------
#define TP64 144u
#define GTILE 18432u
#define GSTG  36864u
#define GEMM_SMEM 110592
__device__ __forceinline__ void load_tile64(uint32_t dst, const __half* src, int stride_h, int t)
{
#pragma unroll
    for (int i = 0; i < 4; ++i) {
        int idx = i * 256 + t;
        int row = idx >> 3, c16 = idx & 7;
        CPA(dst + (uint32_t)row * TP64 + (uint32_t)c16 * 16u, src + (size_t)row * stride_h + c16 * 8);
    }
}

__device__ __forceinline__ void wgemm64(uint32_t As, uint32_t Bs, float C[4][4][4], int lane,
                                        int m0, int n0)
{
    int lr = (lane & 7) + ((lane >> 3) & 1) * 8;
    int akb = ((lane >> 4) & 1) * 8;
    int br = (lane & 7) + ((lane >> 4) & 1) * 8;
    int bkb = ((lane >> 3) & 1) * 8;
#pragma unroll
    for (int ks = 0; ks < 4; ++ks) {
        uint32_t a[4][4];
#pragma unroll
        for (int mi = 0; mi < 4; ++mi)
            LDSM4(a[mi][0], a[mi][1], a[mi][2], a[mi][3],
                  As + (uint32_t)(m0 + mi * 16 + lr) * TP64 + (uint32_t)((ks * 16 + akb) * 2));
#pragma unroll
        for (int np = 0; np < 2; ++np) {
            uint32_t b0, b1, b2, b3;
            LDSM4(b0, b1, b2, b3,
                  Bs + (uint32_t)(n0 + np * 16 + br) * TP64 + (uint32_t)((ks * 16 + bkb) * 2));
#pragma unroll
            for (int mi = 0; mi < 4; ++mi) {
                mma16(C[mi][np * 2], a[mi], b0, b1);
                mma16(C[mi][np * 2 + 1], a[mi], b2, b3);
            }
        }
    }
}

// ---------------- qkv conv GEMM (unchanged) ----------------
__global__ __launch_bounds__(256, 2) void qkv_tc()
{
    extern __shared__ float sm[];
    uint32_t sb = smem_u32(sm);
    int t = threadIdx.x, wid = t >> 5, lane = t & 31;
    int lt = blockIdx.x, rb = blockIdx.y, ng = blockIdx.z;
    int n = ng >> 3, g = ng & 7;
    int l0 = lt * 128;
    int m0 = (wid & 1) * 64, n0 = (wid >> 1) * 32;
    const __half* Ag = g_wg + (size_t)(g * 256 + rb * 128) * 128;
    const __half* Bg = g_tokT + ((size_t)(n * 1024 + l0)) * 1024 + g * 128;

    float C[4][4][4] = {};
    load_tile64(sb, Ag, 128, t);
    load_tile64(sb + GTILE, Bg, 1024, t);
    CPC();
    load_tile64(sb + GSTG, Ag + 64, 128, t);
    load_tile64(sb + GSTG + GTILE, Bg + 64, 1024, t);
    CPC();
    for (int c = 0; c < 2; ++c) {
        if (c == 0) CPW1(); else CPW0();
        __syncthreads();
        uint32_t As = sb + (uint32_t)c * GSTG;
        wgemm64(As, As + GTILE, C, lane, m0, n0);
    }
    __syncthreads();

    float* Sb = sm;  // [128][33]
    int r4 = lane >> 2, j = lane & 3;
    for (int ch = 0; ch < 4; ++ch) {
        if ((wid >> 1) == ch) {
#pragma unroll
            for (int mi = 0; mi < 4; ++mi)
#pragma unroll
                for (int ni = 0; ni < 4; ++ni) {
                    int m = m0 + mi * 16 + r4;
                    int q = ni * 8 + 2 * j;
                    Sb[m * 33 + q] = C[mi][ni][0];
                    Sb[m * 33 + q + 1] = C[mi][ni][1];
                    Sb[(m + 8) * 33 + q] = C[mi][ni][2];
                    Sb[(m + 8) * 33 + q + 1] = C[mi][ni][3];
                }
        }
        __syncthreads();
        if (rb == 0) {
#pragma unroll
            for (int i = 0; i < 8; ++i) {
                int m = t & 63, l = (t >> 6) + 4 * i;
                int h = 2 * g + (m >> 5), d = m & 31;
                size_t base = (((size_t)(n * 16 + h)) * 1024 + l0 + ch * 32 + l) * 32 + d;
                g_kbuf[base] = __float2half(Sb[m * 33 + l] + g_bg[g * 256 + m]);
                g_qbuf[base] = __float2half(Sb[(m + 64) * 33 + l] + g_bg[g * 256 + 64 + m]);
            }
        } else {
#pragma unroll
            for (int i = 0; i < 16; ++i) {
                int l = t & 31, m = (t >> 5) + 8 * i;
                g_vbuf[((size_t)(n * 1024 + g * 128 + m)) * 1024 + l0 + ch * 32 + l] =
                    __float2half(Sb[m * 33 + l] + g_bg[g * 256 + 128 + m]);
            }
        }
        __syncthreads();
    }
}

// ---------------- ff conv: 64x128 tile, 256 thr, 3 CTAs/SM, bulk 3-stage ----------------
#define FA2 8192u
#define FB2 16384u
#define FSTG2 24576u
#define FCONV_SMEM 73728
#define SWA(row, ch) (((uint32_t)(row) << 7) + (uint32_t)(((ch) ^ ((row) & 7)) << 4))

__global__ __launch_bounds__(256, 3) void fconv_tc(float* __restrict__ out)
{
    extern __shared__ float sm[];
    uint32_t sb = smem_u32(sm);
    __shared__ __align__(8) uint64_t s_mbar[3];
    int t = threadIdx.x, wid = t >> 5, lane = t & 31;
    int lt = blockIdx.x, cb2 = blockIdx.y, n = blockIdx.z;
    int l0 = lt * 128;
    int cb = cb2 >> 1, mofs = (cb2 & 1) * 64;
    int m0 = (wid & 1) * 32, n0 = (wid >> 1) * 32;
    const __half* Ag = g_wfb + (size_t)(cb * 16) * 128 * 64 + (size_t)mofs * 64;
    const __half* Bg = g_t2b + (size_t)(n * 16) * 1024 * 64 + (size_t)l0 * 64;

    if (t == 0) {
#pragma unroll
        for (int s = 0; s < 3; ++s) MBAR_INIT(smem_u32(&s_mbar[s]), 1);
    }
    __syncthreads();
    if (t == 0) {
#pragma unroll
        for (int c = 0; c < 2; ++c) {
            uint32_t mb = smem_u32(&s_mbar[c]);
            MBAR_EXPECT(mb, FSTG2);
            CPBULK(sb + (uint32_t)c * FSTG2, Ag + (size_t)c * 8192, FA2, mb);
            CPBULK(sb + (uint32_t)c * FSTG2 + FA2, Bg + (size_t)c * 65536, FB2, mb);
        }
    }

    float C[2][4][4] = {};
    int lr = (lane & 7) + ((lane >> 3) & 1) * 8;
    int akb8 = (lane >> 4) & 1;
    int br = (lane & 7) + ((lane >> 4) & 1) * 8;
    int bkb8 = (lane >> 3) & 1;

    for (int c = 0; c < 16; ++c) {
        int st = c % 3;
        MBAR_WAIT(smem_u32(&s_mbar[st]), (c / 3) & 1);
        __syncthreads();
        if (t == 0 && c + 2 < 16) {
            int nc = c + 2, ns = nc % 3;
            uint32_t mb = smem_u32(&s_mbar[ns]);
            MBAR_EXPECT(mb, FSTG2);
            CPBULK(sb + (uint32_t)ns * FSTG2, Ag + (size_t)nc * 8192, FA2, mb);
            CPBULK(sb + (uint32_t)ns * FSTG2 + FA2, Bg + (size_t)nc * 65536, FB2, mb);
        }
        uint32_t As = sb + (uint32_t)st * FSTG2;
        uint32_t Bs = As + FA2;
#pragma unroll
        for (int ks = 0; ks < 4; ++ks) {
            uint32_t a[2][4];
#pragma unroll
            for (int mi = 0; mi < 2; ++mi) {
                int row = m0 + mi * 16 + lr;
                LDSM4(a[mi][0], a[mi][1], a[mi][2], a[mi][3], As + SWA(row, ks * 2 + akb8));
            }
#pragma unroll
            for (int np = 0; np < 2; ++np) {
                int row = n0 + np * 16 + br;
                uint32_t b0, b1, b2, b3;
                LDSM4(b0, b1, b2, b3, Bs + SWA(row, ks * 2 + bkb8));
#pragma unroll
                for (int mi = 0; mi < 2; ++mi) {
                    mma16(C[mi][np * 2], a[mi], b0, b1);
                    mma16(C[mi][np * 2 + 1], a[mi], b2, b3);
                }
            }
        }
    }
    __syncthreads();

    float* Sb = sm;   // [64][33] fp32
    int r4 = lane >> 2, j = lane & 3;
    for (int ch = 0; ch < 4; ++ch) {
        if ((wid >> 1) == ch) {
#pragma unroll
            for (int mi = 0; mi < 2; ++mi)
#pragma unroll
                for (int ni = 0; ni < 4; ++ni) {
                    int m = m0 + mi * 16 + r4;
                    int q = ni * 8 + 2 * j;
                    Sb[m * 33 + q] = C[mi][ni][0];
                    Sb[m * 33 + q + 1] = C[mi][ni][1];
                    Sb[(m + 8) * 33 + q] = C[mi][ni][2];
                    Sb[(m + 8) * 33 + q + 1] = C[mi][ni][3];
                }
        }
        __syncthreads();
#pragma unroll
        for (int i = 0; i < 8; ++i) {
            int l = t & 31, m = (t >> 5) + 8 * i;
            size_t addr = ((size_t)(n * 1024 + cb2 * 64 + m)) * 1024 + l0 + ch * 32 + l;
            out[addr] = Sb[m * 33 + l] + g_bf[cb2 * 64 + m] + g_t2[addr];
        }
        __syncthreads();
    }
}

// ---------------- flash attention: 4-stage, paired tiles (R9) ----------------
#define TPK 80u
#define KST 5120u
#define AST 14336u
#define ATTN_SMEM 57344

__device__ __forceinline__ void attn_load(uint32_t sb, const __half* Kg, const __half* Vg,
                                          int kt, int st, int t)
{
    uint32_t base = sb + (uint32_t)st * AST;
    int k0 = kt * 64;
    int row = t >> 2, c16 = t & 3;
    CPA(base + (uint32_t)row * TPK + (uint32_t)c16 * 16u, Kg + (size_t)(k0 + row) * 32 + c16 * 8);
#pragma unroll
    for (int i = 0; i < 2; ++i) {
        int idx = i * 256 + t;
        int vr = idx >> 3, vc = idx & 7;
        CPA(base + KST + (uint32_t)(vr * 144 + vc * 16), Vg + (size_t)vr * 1024 + k0 + vc * 8);
    }
    CPC();
}

__global__ __launch_bounds__(256, 2) void attn_tc(const float* __restrict__ tokens)
{
    extern __shared__ float sm[];
    uint32_t sb = smem_u32(sm);

    int t = threadIdx.x, wid = t >> 5, lane = t & 31;
    int r4 = lane >> 2, j = lane & 3;
    int qt = blockIdx.x, h = blockIdx.y, n = blockIdx.z;
    int q0g = qt * 128, q0w = wid * 16;
    const __half* Kg = g_kbuf + ((size_t)(n * 16 + h)) * 1024 * 32;
    const __half* Qg = g_qbuf + ((size_t)(n * 16 + h)) * 1024 * 32;
    const __half* Vg = g_vbuf + ((size_t)(n * 1024 + h * 64)) * 1024;

    uint32_t aq[2][4];
#pragma unroll
    for (int ds = 0; ds < 2; ++ds) {
        const __half* qb = Qg + (size_t)(q0g + q0w + r4) * 32 + ds * 16 + 2 * j;
        aq[ds][0] = *(const uint32_t*)qb;
        aq[ds][1] = *(const uint32_t*)(qb + 8 * 32);
        aq[ds][2] = *(const uint32_t*)(qb + 8);
        aq[ds][3] = *(const uint32_t*)(qb + 8 * 32 + 8);
    }

    attn_load(sb, Kg, Vg, 0, 0, t);
    attn_load(sb, Kg, Vg, 1, 1, t);

    float CO[8][4] = {};
    float mo0 = -1e30f, mo1 = -1e30f, l0 = 0.f, l1 = 0.f;
    int lr = (lane & 7) + ((lane >> 4) & 1) * 8;
    int kbo = ((lane >> 3) & 1) * 8;

    for (int pr = 0; pr < 8; ++pr) {
        CPW0();
        __syncthreads();
        if (pr < 7) {
            attn_load(sb, Kg, Vg, 2 * pr + 2, (2 * pr + 2) & 3, t);
            attn_load(sb, Kg, Vg, 2 * pr + 3, (2 * pr + 3) & 3, t);
        }
#pragma unroll
        for (int sub = 0; sub < 2; ++sub) {
            int kt = 2 * pr + sub;
            uint32_t ksm = sb + (uint32_t)(kt & 3) * AST;
            uint32_t vsm = ksm + KST;

            float CS[8][4] = {};
#pragma unroll
            for (int ds = 0; ds < 2; ++ds)
#pragma unroll
                for (int ntp = 0; ntp < 4; ++ntp) {
                    uint32_t b0, b1, b2, b3;
                    LDSM4(b0, b1, b2, b3,
                          ksm + (uint32_t)(ntp * 16 + lr) * TPK + (uint32_t)((ds * 16 + kbo) * 2));
                    mma16(CS[2 * ntp], aq[ds], b0, b1);
                    mma16(CS[2 * ntp + 1], aq[ds], b2, b3);
                }

            float mt0 = -1e30f, mt1 = -1e30f;
#pragma unroll
            for (int nt = 0; nt < 8; ++nt) {
                mt0 = fmaxf(mt0, fmaxf(CS[nt][0], CS[nt][1]));
                mt1 = fmaxf(mt1, fmaxf(CS[nt][2], CS[nt][3]));
            }
            mt0 = fmaxf(mt0, __shfl_xor_sync(0xffffffffu, mt0, 1));
            mt0 = fmaxf(mt0, __shfl_xor_sync(0xffffffffu, mt0, 2));
            mt1 = fmaxf(mt1, __shfl_xor_sync(0xffffffffu, mt1, 1));
            mt1 = fmaxf(mt1, __shfl_xor_sync(0xffffffffu, mt1, 2));
            float mn0 = fmaxf(mo0, mt0), mn1 = fmaxf(mo1, mt1);
            float nm0 = -mn0 * L2E, nm1 = -mn1 * L2E;
            float fac0 = ex2f(fmaf(mo0, L2E, nm0));
            float fac1 = ex2f(fmaf(mo1, L2E, nm1));
            float s0 = 0.f, s1 = 0.f;
#pragma unroll
            for (int nt = 0; nt < 8; ++nt) {
                float e0 = ex2f(fmaf(CS[nt][0], L2E, nm0));
                float e1 = ex2f(fmaf(CS[nt][1], L2E, nm0));
                float e2 = ex2f(fmaf(CS[nt][2], L2E, nm1));
                float e3 = ex2f(fmaf(CS[nt][3], L2E, nm1));
                s0 += e0 + e1; s1 += e2 + e3;
                CS[nt][0] = e0; CS[nt][1] = e1; CS[nt][2] = e2; CS[nt][3] = e3;
            }
            s0 += __shfl_xor_sync(0xffffffffu, s0, 1);
            s0 += __shfl_xor_sync(0xffffffffu, s0, 2);
            s1 += __shfl_xor_sync(0xffffffffu, s1, 1);
            s1 += __shfl_xor_sync(0xffffffffu, s1, 2);
            l0 = l0 * fac0 + s0; l1 = l1 * fac1 + s1;
            mo0 = mn0; mo1 = mn1;
#pragma unroll
            for (int nt = 0; nt < 8; ++nt) {
                CO[nt][0] *= fac0; CO[nt][1] *= fac0;
                CO[nt][2] *= fac1; CO[nt][3] *= fac1;
            }

#pragma unroll
            for (int kc = 0; kc < 4; ++kc) {
                uint32_t ap[4];
                ap[0] = packh2(CS[2 * kc][0], CS[2 * kc][1]);
                ap[1] = packh2(CS[2 * kc][2], CS[2 * kc][3]);
                ap[2] = packh2(CS[2 * kc + 1][0], CS[2 * kc + 1][1]);
                ap[3] = packh2(CS[2 * kc + 1][2], CS[2 * kc + 1][3]);
#pragma unroll
                for (int ntp = 0; ntp < 4; ++ntp) {
                    uint32_t b0, b1, b2, b3;
                    LDSM4(b0, b1, b2, b3,
                          vsm + (uint32_t)((ntp * 16 + lr) * 144 + (kc * 16 + kbo) * 2));
                    mma16(CO[2 * ntp], ap, b0, b1);
                    mma16(CO[2 * ntp + 1], ap, b2, b3);
                }
            }
        }
    }

    __syncthreads();
    float* Ob = sm;  // [64][133]
    float li0 = 1.0f / l0, li1 = 1.0f / l1;
#pragma unroll
    for (int nt = 0; nt < 8; ++nt) {
        int d = nt * 8 + 2 * j;
        int q = q0w + r4;
        Ob[d * 133 + q] = CO[nt][0] * li0;
        Ob[(d + 1) * 133 + q] = CO[nt][1] * li0;
        Ob[d * 133 + q + 8] = CO[nt][2] * li1;
        Ob[(d + 1) * 133 + q + 8] = CO[nt][3] * li1;
    }
    __syncthreads();
#pragma unroll
    for (int i = 0; i < 32; ++i) {
        int q = t & 127, d = (t >> 7) + 2 * i;
        size_t addr = ((size_t)(n * 1024 + h * 64 + d)) * 1024 + q0g + q;
        float r = tokens[addr] + Ob[d * 133 + q];
        g_t2[addr] = r;
        Ob[d * 133 + q] = r;
    }
    __syncthreads();
    // blocked + pre-swizzled t2 transpose for fconv bulk loads
#pragma unroll
    for (int i = 0; i < 32; ++i) {
        int d = t & 63, l = (t >> 6) + 4 * i;
        int lg = q0g + l;
        size_t dst = ((size_t)(n * 16 + h) * 1024 + lg) * 64 + (((d >> 3) ^ (lg & 7)) << 3) + (d & 7);
        g_t2b[dst] = __float2half(Ob[d * 133 + l]);
    }
}

// ---------------- launch ----------------
extern "C" void kernel_launch(void* const* d_in, const int* in_sizes, int n_in,
                              void* d_out, int out_size)
{
    (void)in_sizes; (void)n_in; (void)out_size;
    const float* tokens = (const float*)d_in[0];
    const float* p[24];
    for (int i = 0; i < 24; ++i) p[i] = (const float*)d_in[1 + i];

    cudaFuncSetAttribute(qkv_tc, cudaFuncAttributeMaxDynamicSharedMemorySize, GEMM_SMEM);
    cudaFuncSetAttribute(fconv_tc, cudaFuncAttributeMaxDynamicSharedMemorySize, FCONV_SMEM);
    cudaFuncSetAttribute(attn_tc, cudaFuncAttributeMaxDynamicSharedMemorySize, ATTN_SMEM);

    int prep_blocks = TRANS_BLOCKS + (1024 * 1024 + 8 * 256 * 128 + 8 * 256 + 1024 + 255) / 256;
    prep_kernel<<<prep_blocks, 256>>>(tokens,
        p[0], p[1], p[2], p[3], p[4], p[5],
        p[6], p[7], p[8], p[9], p[10], p[11],
        p[12], p[13], p[14], p[15], p[16], p[17],
        p[18], p[19], p[20], p[21], p[22], p[23]);

    qkv_tc<<<dim3(8, 2, 64), 256, GEMM_SMEM>>>();
    attn_tc<<<dim3(8, 16, 8), 256, ATTN_SMEM>>>(tokens);
    fconv_tc<<<dim3(8, 16, 8), 256, FCONV_SMEM>>>((float*)d_out);
}

// round 13
// speedup vs baseline: 1.1426x; 1.0164x over previous
#include <cuda_runtime.h>
#include <cuda_fp16.h>
#include <cstdint>
#include <math.h>

// ---------------- scratch ----------------
__device__ __half g_kbuf[8 * 16 * 1024 * 32];   // [n][h][l][d]
__device__ __half g_qbuf[8 * 16 * 1024 * 32];   // [n][h][l][d] (pre-scaled 1/32)
__device__ __half g_vbuf[8 * 1024 * 1024];      // [n][c][l]
__device__ float  g_t2 [8 * 1024 * 1024];       // [n][c][l] fp32 residual
__device__ __half g_t2b[8 * 1024 * 1024];       // blocked+swizzled [n][kc16][l][64h]
__device__ __half g_tokT[8 * 1024 * 1024];      // [n][l][c]
__device__ __half g_wg[8 * 256 * 128];          // [g][r][k]
__device__ float  g_bg[8 * 256];
__device__ __half g_wfb[1024 * 1024];           // blocked+swizzled [cb8][kc16][m128][64h]
__device__ float  g_bf[1024];

// ---------------- helpers ----------------
__device__ __forceinline__ uint32_t smem_u32(const void* p) {
    uint32_t a;
    asm("{ .reg .u64 t; cvta.to.shared.u64 t, %1; cvt.u32.u64 %0, t; }" : "=r"(a) : "l"(p));
    return a;
}
#define CPA(dst, src) asm volatile("cp.async.cg.shared.global [%0], [%1], 16;" :: "r"(dst), "l"(__cvta_generic_to_global(src)))
#define CPC()  asm volatile("cp.async.commit_group;" ::: "memory")
#define CPW0() asm volatile("cp.async.wait_group 0;" ::: "memory")
#define CPW1() asm volatile("cp.async.wait_group 1;" ::: "memory")
#define LDSM4(r0, r1, r2, r3, a) \
    asm volatile("ldmatrix.sync.aligned.m8n8.x4.shared.b16 {%0,%1,%2,%3}, [%4];" \
        : "=r"(r0), "=r"(r1), "=r"(r2), "=r"(r3) : "r"(a))

#define MBAR_INIT(a, c) asm volatile("mbarrier.init.shared.b64 [%0], %1;" :: "r"(a), "r"(c) : "memory")
#define MBAR_EXPECT(a, bytes) \
    asm volatile("mbarrier.arrive.expect_tx.shared.b64 _, [%0], %1;" :: "r"(a), "r"(bytes) : "memory")
#define CPBULK(dstS, srcG, bytes, mbar) \
    asm volatile("cp.async.bulk.shared::cta.global.mbarrier::complete_tx::bytes [%0], [%1], %2, [%3];" \
        :: "r"(dstS), "l"(__cvta_generic_to_global(srcG)), "r"(bytes), "r"(mbar) : "memory")
#define MBAR_WAIT(mbar_addr, parity) do { \
    uint32_t _m = (mbar_addr), _p = (parity), _d; \
    asm volatile("{\n\t.reg .pred p;\n\t" \
        "mbarrier.try_wait.parity.acquire.cta.shared::cta.b64 p, [%1], %2;\n\t" \
        "selp.b32 %0, 1, 0, p;\n\t}" : "=r"(_d) : "r"(_m), "r"(_p) : "memory"); \
    if (!_d) { \
        asm volatile("{\n\t.reg .pred P1;\n\t" \
            "WL_%=:\n\t" \
            "mbarrier.try_wait.parity.acquire.cta.shared::cta.b64 P1, [%0], %1, 0x989680;\n\t" \
            "@P1 bra.uni WD_%=;\n\t" \
            "bra.uni WL_%=;\n\t" \
            "WD_%=:\n\t}" :: "r"(_m), "r"(_p) : "memory"); \
    } \
} while (0)

__device__ __forceinline__ void mma16(float* d, const uint32_t* a, uint32_t b0, uint32_t b1) {
    asm volatile(
        "mma.sync.aligned.m16n8k16.row.col.f32.f16.f16.f32 "
        "{%0,%1,%2,%3}, {%4,%5,%6,%7}, {%8,%9}, {%0,%1,%2,%3};"
        : "+f"(d[0]), "+f"(d[1]), "+f"(d[2]), "+f"(d[3])
        : "r"(a[0]), "r"(a[1]), "r"(a[2]), "r"(a[3]), "r"(b0), "r"(b1));
}
__device__ __forceinline__ uint32_t packh2(float a, float b) {
    __half2 h = __floats2half2_rn(a, b);
    return *(uint32_t*)&h;
}
__device__ __forceinline__ float ex2f(float x) {
    float r;
    asm("ex2.approx.f32 %0, %1;" : "=f"(r) : "f"(x));
    return r;
}
#define L2E 1.4426950408889634f

// ---------------- fused prep + tokens transpose ----------------
#define TRANS_BLOCKS 8192
__global__ __launch_bounds__(256) void prep_kernel(
    const float* __restrict__ tokens,
    const float* __restrict__ kw, const float* __restrict__ kb, const float* __restrict__ kga,
    const float* __restrict__ kbe, const float* __restrict__ km, const float* __restrict__ kv,
    const float* __restrict__ qw, const float* __restrict__ qb, const float* __restrict__ qga,
    const float* __restrict__ qbe, const float* __restrict__ qm, const float* __restrict__ qv,
    const float* __restrict__ vw, const float* __restrict__ vb, const float* __restrict__ vga,
    const float* __restrict__ vbe, const float* __restrict__ vm, const float* __restrict__ vv,
    const float* __restrict__ fw, const float* __restrict__ fb, const float* __restrict__ fga,
    const float* __restrict__ fbe, const float* __restrict__ fm, const float* __restrict__ fv)
{
    __shared__ float tile[32][33];
    int t = threadIdx.x;
    if (blockIdx.x < TRANS_BLOCKS) {
        int bid = blockIdx.x;
        int l0 = (bid & 31) * 32, c0 = ((bid >> 5) & 31) * 32, n = bid >> 10;
#pragma unroll
        for (int i = 0; i < 4; ++i) {
            int idx = i * 256 + t;
            int r = idx >> 5, col = idx & 31;
            tile[r][col] = tokens[((size_t)(n * 1024 + c0 + r)) * 1024 + l0 + col];
        }
        __syncthreads();
#pragma unroll
        for (int i = 0; i < 4; ++i) {
            int idx = i * 256 + t;
            int r = idx >> 5, col = idx & 31;
            g_tokT[((size_t)(n * 1024 + l0 + r)) * 1024 + c0 + col] = __float2half(tile[col][r]);
        }
        return;
    }
    int id = (blockIdx.x - TRANS_BLOCKS) * 256 + t;
    if (id < 1024 * 1024) {
        int k = id & 1023, c = id >> 10;
        float inv = fga[c] * rsqrtf(fv[c] + 1e-5f);
        int cb = c >> 7, m = c & 127, kc = k >> 6, ch = (k >> 3) & 7, w = k & 7;
        size_t dst = ((size_t)((cb * 16 + kc) * 128 + m)) * 64 + ((ch ^ (m & 7)) << 3) + w;
        g_wfb[dst] = __float2half(fw[id] * inv);
        return;
    }
    int id2 = id - 1024 * 1024;
    if (id2 < 8 * 256 * 128) {
        int k = id2 & 127;
        int r = (id2 >> 7) & 255;
        int g = id2 >> 15;
        float w;
        if (r < 64) {
            int c = g * 64 + r;
            float inv = kga[c] * rsqrtf(kv[c] + 1e-5f);
            w = kw[c * 128 + k] * inv;
        } else if (r < 128) {
            int c = g * 64 + (r - 64);
            float inv = qga[c] * rsqrtf(qv[c] + 1e-5f);
            w = qw[c * 128 + k] * inv * 0.03125f;
        } else {
            int c = g * 128 + (r - 128);
            float inv = vga[c] * rsqrtf(vv[c] + 1e-5f);
            w = vw[c * 128 + k] * inv;
        }
        g_wg[id2] = __float2half(w);
        return;
    }
    int id3 = id2 - 8 * 256 * 128;
    if (id3 < 8 * 256) {
        int g = id3 >> 8, r = id3 & 255;
        float bias;
        if (r < 64) {
            int c = g * 64 + r;
            float inv = kga[c] * rsqrtf(kv[c] + 1e-5f);
            bias = kb[c] * inv + kbe[c] - km[c] * inv;
        } else if (r < 128) {
            int c = g * 64 + (r - 64);
            float inv = qga[c] * rsqrtf(qv[c] + 1e-5f);
            bias = (qb[c] * inv + qbe[c] - qm[c] * inv) * 0.03125f;
        } else {
            int c = g * 128 + (r - 128);
            float inv = vga[c] * rsqrtf(vv[c] + 1e-5f);
            bias = vb[c] * inv + vbe[c] - vm[c] * inv;
        }
        g_bg[id3] = bias;
        return;
    }
    int c = id3 - 8 * 256;
    if (c < 1024) {
        float inv = fga[c] * rsqrtf(fv[c] + 1e-5f);
        g_bf[c] = fb[c] * inv + fbe[c] - fm[c] * inv;
    }
}

// ---------------- GEMM pieces (fp16, ldmatrix, K-chunk 64, padded pitch) ----------------
#define TP64 144u
#define GTILE 18432u
#define GSTG  36864u
#define GEMM_SMEM 110592
__device__ __forceinline__ void load_tile64(uint32_t dst, const __half* src, int stride_h, int t)
{
#pragma unroll
    for (int i = 0; i < 4; ++i) {
        int idx = i * 256 + t;
        int row = idx >> 3, c16 = idx & 7;
        CPA(dst + (uint32_t)row * TP64 + (uint32_t)c16 * 16u, src + (size_t)row * stride_h + c16 * 8);
    }
}

__device__ __forceinline__ void wgemm64(uint32_t As, uint32_t Bs, float C[4][4][4], int lane,
                                        int m0, int n0)
{
    int lr = (lane & 7) + ((lane >> 3) & 1) * 8;
    int akb = ((lane >> 4) & 1) * 8;
    int br = (lane & 7) + ((lane >> 4) & 1) * 8;
    int bkb = ((lane >> 3) & 1) * 8;
#pragma unroll
    for (int ks = 0; ks < 4; ++ks) {
        uint32_t a[4][4];
#pragma unroll
        for (int mi = 0; mi < 4; ++mi)
            LDSM4(a[mi][0], a[mi][1], a[mi][2], a[mi][3],
                  As + (uint32_t)(m0 + mi * 16 + lr) * TP64 + (uint32_t)((ks * 16 + akb) * 2));
#pragma unroll
        for (int np = 0; np < 2; ++np) {
            uint32_t b0, b1, b2, b3;
            LDSM4(b0, b1, b2, b3,
                  Bs + (uint32_t)(n0 + np * 16 + br) * TP64 + (uint32_t)((ks * 16 + bkb) * 2));
#pragma unroll
            for (int mi = 0; mi < 4; ++mi) {
                mma16(C[mi][np * 2], a[mi], b0, b1);
                mma16(C[mi][np * 2 + 1], a[mi], b2, b3);
            }
        }
    }
}

// ---------------- qkv conv GEMM (unchanged) ----------------
__global__ __launch_bounds__(256, 2) void qkv_tc()
{
    extern __shared__ float sm[];
    uint32_t sb = smem_u32(sm);
    int t = threadIdx.x, wid = t >> 5, lane = t & 31;
    int lt = blockIdx.x, rb = blockIdx.y, ng = blockIdx.z;
    int n = ng >> 3, g = ng & 7;
    int l0 = lt * 128;
    int m0 = (wid & 1) * 64, n0 = (wid >> 1) * 32;
    const __half* Ag = g_wg + (size_t)(g * 256 + rb * 128) * 128;
    const __half* Bg = g_tokT + ((size_t)(n * 1024 + l0)) * 1024 + g * 128;

    float C[4][4][4] = {};
    load_tile64(sb, Ag, 128, t);
    load_tile64(sb + GTILE, Bg, 1024, t);
    CPC();
    load_tile64(sb + GSTG, Ag + 64, 128, t);
    load_tile64(sb + GSTG + GTILE, Bg + 64, 1024, t);
    CPC();
    for (int c = 0; c < 2; ++c) {
        if (c == 0) CPW1(); else CPW0();
        __syncthreads();
        uint32_t As = sb + (uint32_t)c * GSTG;
        wgemm64(As, As + GTILE, C, lane, m0, n0);
    }
    __syncthreads();

    float* Sb = sm;  // [128][33]
    int r4 = lane >> 2, j = lane & 3;
    for (int ch = 0; ch < 4; ++ch) {
        if ((wid >> 1) == ch) {
#pragma unroll
            for (int mi = 0; mi < 4; ++mi)
#pragma unroll
                for (int ni = 0; ni < 4; ++ni) {
                    int m = m0 + mi * 16 + r4;
                    int q = ni * 8 + 2 * j;
                    Sb[m * 33 + q] = C[mi][ni][0];
                    Sb[m * 33 + q + 1] = C[mi][ni][1];
                    Sb[(m + 8) * 33 + q] = C[mi][ni][2];
                    Sb[(m + 8) * 33 + q + 1] = C[mi][ni][3];
                }
        }
        __syncthreads();
        if (rb == 0) {
#pragma unroll
            for (int i = 0; i < 8; ++i) {
                int m = t & 63, l = (t >> 6) + 4 * i;
                int h = 2 * g + (m >> 5), d = m & 31;
                size_t base = (((size_t)(n * 16 + h)) * 1024 + l0 + ch * 32 + l) * 32 + d;
                g_kbuf[base] = __float2half(Sb[m * 33 + l] + g_bg[g * 256 + m]);
                g_qbuf[base] = __float2half(Sb[(m + 64) * 33 + l] + g_bg[g * 256 + 64 + m]);
            }
        } else {
#pragma unroll
            for (int i = 0; i < 16; ++i) {
                int l = t & 31, m = (t >> 5) + 8 * i;
                g_vbuf[((size_t)(n * 1024 + g * 128 + m)) * 1024 + l0 + ch * 32 + l] =
                    __float2half(Sb[m * 33 + l] + g_bg[g * 256 + 128 + m]);
            }
        }
        __syncthreads();
    }
}

// ---------------- ff conv: 64x128 tile, 512 thr, 2 CTAs/SM (32 warps), bulk 4-stage ----------------
#define FA2 8192u
#define FB2 16384u
#define FSTG2 24576u
#define FCONV_SMEM 98304
#define SWA(row, ch) (((uint32_t)(row) << 7) + (uint32_t)(((ch) ^ ((row) & 7)) << 4))

__global__ __launch_bounds__(512, 2) void fconv_tc(float* __restrict__ out)
{
    extern __shared__ float sm[];
    uint32_t sb = smem_u32(sm);
    __shared__ __align__(8) uint64_t s_mbar[4];
    int t = threadIdx.x, wid = t >> 5, lane = t & 31;
    int lt = blockIdx.x, cb2 = blockIdx.y, n = blockIdx.z;
    int l0 = lt * 128;
    int cb = cb2 >> 1, mofs = (cb2 & 1) * 64;
    int m0 = (wid & 1) * 32, n0 = (wid >> 1) * 16;
    const __half* Ag = g_wfb + (size_t)(cb * 16) * 128 * 64 + (size_t)mofs * 64;
    const __half* Bg = g_t2b + (size_t)(n * 16) * 1024 * 64 + (size_t)l0 * 64;

    if (t == 0) {
#pragma unroll
        for (int s = 0; s < 4; ++s) MBAR_INIT(smem_u32(&s_mbar[s]), 1);
    }
    __syncthreads();
    if (t == 0) {
#pragma unroll
        for (int c = 0; c < 3; ++c) {
            uint32_t mb = smem_u32(&s_mbar[c]);
            MBAR_EXPECT(mb, FSTG2);
            CPBULK(sb + (uint32_t)c * FSTG2, Ag + (size_t)c * 8192, FA2, mb);
            CPBULK(sb + (uint32_t)c * FSTG2 + FA2, Bg + (size_t)c * 65536, FB2, mb);
        }
    }

    float C[2][2][4] = {};
    int lr = (lane & 7) + ((lane >> 3) & 1) * 8;
    int akb8 = (lane >> 4) & 1;
    int br = (lane & 7) + ((lane >> 4) & 1) * 8;
    int bkb8 = (lane >> 3) & 1;

    for (int c = 0; c < 16; ++c) {
        int st = c & 3;
        MBAR_WAIT(smem_u32(&s_mbar[st]), (c >> 2) & 1);
        __syncthreads();
        if (t == 0 && c + 3 < 16) {
            int nc = c + 3, ns = nc & 3;
            uint32_t mb = smem_u32(&s_mbar[ns]);
            MBAR_EXPECT(mb, FSTG2);
            CPBULK(sb + (uint32_t)ns * FSTG2, Ag + (size_t)nc * 8192, FA2, mb);
            CPBULK(sb + (uint32_t)ns * FSTG2 + FA2, Bg + (size_t)nc * 65536, FB2, mb);
        }
        uint32_t As = sb + (uint32_t)st * FSTG2;
        uint32_t Bs = As + FA2;
#pragma unroll
        for (int ks = 0; ks < 4; ++ks) {
            uint32_t a[2][4];
#pragma unroll
            for (int mi = 0; mi < 2; ++mi) {
                int row = m0 + mi * 16 + lr;
                LDSM4(a[mi][0], a[mi][1], a[mi][2], a[mi][3], As + SWA(row, ks * 2 + akb8));
            }
            uint32_t b0, b1, b2, b3;
            {
                int row = n0 + br;
                LDSM4(b0, b1, b2, b3, Bs + SWA(row, ks * 2 + bkb8));
            }
#pragma unroll
            for (int mi = 0; mi < 2; ++mi) {
                mma16(C[mi][0], a[mi], b0, b1);
                mma16(C[mi][1], a[mi], b2, b3);
            }
        }
    }
    __syncthreads();

    // one-pass epilogue: full 64x128 tile in smem
    float* Ob = sm;   // [64][133] fp32
    int r4 = lane >> 2, j = lane & 3;
#pragma unroll
    for (int mi = 0; mi < 2; ++mi)
#pragma unroll
        for (int ni = 0; ni < 2; ++ni) {
            int m = m0 + mi * 16 + r4;
            int q = n0 + ni * 8 + 2 * j;
            Ob[m * 133 + q] = C[mi][ni][0];
            Ob[m * 133 + q + 1] = C[mi][ni][1];
            Ob[(m + 8) * 133 + q] = C[mi][ni][2];
            Ob[(m + 8) * 133 + q + 1] = C[mi][ni][3];
        }
    __syncthreads();
#pragma unroll
    for (int i = 0; i < 16; ++i) {
        int idx = i * 512 + t;
        int m = idx >> 7, l = idx & 127;
        size_t addr = ((size_t)(n * 1024 + cb2 * 64 + m)) * 1024 + l0 + l;
        out[addr] = Ob[m * 133 + l] + g_bf[cb2 * 64 + m] + g_t2[addr];
    }
}

// ---------------- flash attention: 4-stage, paired tiles (R9) ----------------
#define TPK 80u
#define KST 5120u
#define AST 14336u
#define ATTN_SMEM 57344

__device__ __forceinline__ void attn_load(uint32_t sb, const __half* Kg, const __half* Vg,
                                          int kt, int st, int t)
{
    uint32_t base = sb + (uint32_t)st * AST;
    int k0 = kt * 64;
    int row = t >> 2, c16 = t & 3;
    CPA(base + (uint32_t)row * TPK + (uint32_t)c16 * 16u, Kg + (size_t)(k0 + row) * 32 + c16 * 8);
#pragma unroll
    for (int i = 0; i < 2; ++i) {
        int idx = i * 256 + t;
        int vr = idx >> 3, vc = idx & 7;
        CPA(base + KST + (uint32_t)(vr * 144 + vc * 16), Vg + (size_t)vr * 1024 + k0 + vc * 8);
    }
    CPC();
}

__global__ __launch_bounds__(256, 2) void attn_tc(const float* __restrict__ tokens)
{
    extern __shared__ float sm[];
    uint32_t sb = smem_u32(sm);

    int t = threadIdx.x, wid = t >> 5, lane = t & 31;
    int r4 = lane >> 2, j = lane & 3;
    int qt = blockIdx.x, h = blockIdx.y, n = blockIdx.z;
    int q0g = qt * 128, q0w = wid * 16;
    const __half* Kg = g_kbuf + ((size_t)(n * 16 + h)) * 1024 * 32;
    const __half* Qg = g_qbuf + ((size_t)(n * 16 + h)) * 1024 * 32;
    const __half* Vg = g_vbuf + ((size_t)(n * 1024 + h * 64)) * 1024;

    uint32_t aq[2][4];
#pragma unroll
    for (int ds = 0; ds < 2; ++ds) {
        const __half* qb = Qg + (size_t)(q0g + q0w + r4) * 32 + ds * 16 + 2 * j;
        aq[ds][0] = *(const uint32_t*)qb;
        aq[ds][1] = *(const uint32_t*)(qb + 8 * 32);
        aq[ds][2] = *(const uint32_t*)(qb + 8);
        aq[ds][3] = *(const uint32_t*)(qb + 8 * 32 + 8);
    }

    attn_load(sb, Kg, Vg, 0, 0, t);
    attn_load(sb, Kg, Vg, 1, 1, t);

    float CO[8][4] = {};
    float mo0 = -1e30f, mo1 = -1e30f, l0 = 0.f, l1 = 0.f;
    int lr = (lane & 7) + ((lane >> 4) & 1) * 8;
    int kbo = ((lane >> 3) & 1) * 8;

    for (int pr = 0; pr < 8; ++pr) {
        CPW0();
        __syncthreads();
        if (pr < 7) {
            attn_load(sb, Kg, Vg, 2 * pr + 2, (2 * pr + 2) & 3, t);
            attn_load(sb, Kg, Vg, 2 * pr + 3, (2 * pr + 3) & 3, t);
        }
#pragma unroll
        for (int sub = 0; sub < 2; ++sub) {
            int kt = 2 * pr + sub;
            uint32_t ksm = sb + (uint32_t)(kt & 3) * AST;
            uint32_t vsm = ksm + KST;

            float CS[8][4] = {};
#pragma unroll
            for (int ds = 0; ds < 2; ++ds)
#pragma unroll
                for (int ntp = 0; ntp < 4; ++ntp) {
                    uint32_t b0, b1, b2, b3;
                    LDSM4(b0, b1, b2, b3,
                          ksm + (uint32_t)(ntp * 16 + lr) * TPK + (uint32_t)((ds * 16 + kbo) * 2));
                    mma16(CS[2 * ntp], aq[ds], b0, b1);
                    mma16(CS[2 * ntp + 1], aq[ds], b2, b3);
                }

            float mt0 = -1e30f, mt1 = -1e30f;
#pragma unroll
            for (int nt = 0; nt < 8; ++nt) {
                mt0 = fmaxf(mt0, fmaxf(CS[nt][0], CS[nt][1]));
                mt1 = fmaxf(mt1, fmaxf(CS[nt][2], CS[nt][3]));
            }
            mt0 = fmaxf(mt0, __shfl_xor_sync(0xffffffffu, mt0, 1));
            mt0 = fmaxf(mt0, __shfl_xor_sync(0xffffffffu, mt0, 2));
            mt1 = fmaxf(mt1, __shfl_xor_sync(0xffffffffu, mt1, 1));
            mt1 = fmaxf(mt1, __shfl_xor_sync(0xffffffffu, mt1, 2));
            float mn0 = fmaxf(mo0, mt0), mn1 = fmaxf(mo1, mt1);
            float nm0 = -mn0 * L2E, nm1 = -mn1 * L2E;
            float fac0 = ex2f(fmaf(mo0, L2E, nm0));
            float fac1 = ex2f(fmaf(mo1, L2E, nm1));
            float s0 = 0.f, s1 = 0.f;
#pragma unroll
            for (int nt = 0; nt < 8; ++nt) {
                float e0 = ex2f(fmaf(CS[nt][0], L2E, nm0));
                float e1 = ex2f(fmaf(CS[nt][1], L2E, nm0));
                float e2 = ex2f(fmaf(CS[nt][2], L2E, nm1));
                float e3 = ex2f(fmaf(CS[nt][3], L2E, nm1));
                s0 += e0 + e1; s1 += e2 + e3;
                CS[nt][0] = e0; CS[nt][1] = e1; CS[nt][2] = e2; CS[nt][3] = e3;
            }
            s0 += __shfl_xor_sync(0xffffffffu, s0, 1);
            s0 += __shfl_xor_sync(0xffffffffu, s0, 2);
            s1 += __shfl_xor_sync(0xffffffffu, s1, 1);
            s1 += __shfl_xor_sync(0xffffffffu, s1, 2);
            l0 = l0 * fac0 + s0; l1 = l1 * fac1 + s1;
            mo0 = mn0; mo1 = mn1;
#pragma unroll
            for (int nt = 0; nt < 8; ++nt) {
                CO[nt][0] *= fac0; CO[nt][1] *= fac0;
                CO[nt][2] *= fac1; CO[nt][3] *= fac1;
            }

#pragma unroll
            for (int kc = 0; kc < 4; ++kc) {
                uint32_t ap[4];
                ap[0] = packh2(CS[2 * kc][0], CS[2 * kc][1]);
                ap[1] = packh2(CS[2 * kc][2], CS[2 * kc][3]);
                ap[2] = packh2(CS[2 * kc + 1][0], CS[2 * kc + 1][1]);
                ap[3] = packh2(CS[2 * kc + 1][2], CS[2 * kc + 1][3]);
#pragma unroll
                for (int ntp = 0; ntp < 4; ++ntp) {
                    uint32_t b0, b1, b2, b3;
                    LDSM4(b0, b1, b2, b3,
                          vsm + (uint32_t)((ntp * 16 + lr) * 144 + (kc * 16 + kbo) * 2));
                    mma16(CO[2 * ntp], ap, b0, b1);
                    mma16(CO[2 * ntp + 1], ap, b2, b3);
                }
            }
        }
    }

    __syncthreads();
    float* Ob = sm;  // [64][133]
    float li0 = 1.0f / l0, li1 = 1.0f / l1;
#pragma unroll
    for (int nt = 0; nt < 8; ++nt) {
        int d = nt * 8 + 2 * j;
        int q = q0w + r4;
        Ob[d * 133 + q] = CO[nt][0] * li0;
        Ob[(d + 1) * 133 + q] = CO[nt][1] * li0;
        Ob[d * 133 + q + 8] = CO[nt][2] * li1;
        Ob[(d + 1) * 133 + q + 8] = CO[nt][3] * li1;
    }
    __syncthreads();
#pragma unroll
    for (int i = 0; i < 32; ++i) {
        int q = t & 127, d = (t >> 7) + 2 * i;
        size_t addr = ((size_t)(n * 1024 + h * 64 + d)) * 1024 + q0g + q;
        float r = tokens[addr] + Ob[d * 133 + q];
        g_t2[addr] = r;
        Ob[d * 133 + q] = r;
    }
    __syncthreads();
    // blocked + pre-swizzled t2 transpose for fconv bulk loads
#pragma unroll
    for (int i = 0; i < 32; ++i) {
        int d = t & 63, l = (t >> 6) + 4 * i;
        int lg = q0g + l;
        size_t dst = ((size_t)(n * 16 + h) * 1024 + lg) * 64 + (((d >> 3) ^ (lg & 7)) << 3) + (d & 7);
        g_t2b[dst] = __float2half(Ob[d * 133 + l]);
    }
}

// ---------------- launch ----------------
extern "C" void kernel_launch(void* const* d_in, const int* in_sizes, int n_in,
                              void* d_out, int out_size)
{
    (void)in_sizes; (void)n_in; (void)out_size;
    const float* tokens = (const float*)d_in[0];
    const float* p[24];
    for (int i = 0; i < 24; ++i) p[i] = (const float*)d_in[1 + i];

    cudaFuncSetAttribute(qkv_tc, cudaFuncAttributeMaxDynamicSharedMemorySize, GEMM_SMEM);
    cudaFuncSetAttribute(fconv_tc, cudaFuncAttributeMaxDynamicSharedMemorySize, FCONV_SMEM);
    cudaFuncSetAttribute(attn_tc, cudaFuncAttributeMaxDynamicSharedMemorySize, ATTN_SMEM);

    int prep_blocks = TRANS_BLOCKS + (1024 * 1024 + 8 * 256 * 128 + 8 * 256 + 1024 + 255) / 256;
    prep_kernel<<<prep_blocks, 256>>>(tokens,
        p[0], p[1], p[2], p[3], p[4], p[5],
        p[6], p[7], p[8], p[9], p[10], p[11],
        p[12], p[13], p[14], p[15], p[16], p[17],
        p[18], p[19], p[20], p[21], p[22], p[23]);

    qkv_tc<<<dim3(8, 2, 64), 256, GEMM_SMEM>>>();
    attn_tc<<<dim3(8, 16, 8), 256, ATTN_SMEM>>>(tokens);
    fconv_tc<<<dim3(8, 16, 8), 512, FCONV_SMEM>>>((float*)d_out);
}

// round 14
// speedup vs baseline: 1.2162x; 1.0644x over previous
#include <cuda_runtime.h>
#include <cuda_fp16.h>
#include <cstdint>
#include <math.h>

// ---------------- scratch ----------------
__device__ __half g_kbuf[8 * 16 * 1024 * 32];   // [n][h][l][d]
__device__ __half g_qbuf[8 * 16 * 1024 * 32];   // [n][h][l][d] (pre-scaled log2e/32)
__device__ __half g_vbuf[8 * 1024 * 1024];      // [n][c][l]
__device__ float  g_t2 [8 * 1024 * 1024];       // [n][c][l] fp32 residual
__device__ __half g_t2b[8 * 1024 * 1024];       // blocked+swizzled [n][kc16][l][64h]
__device__ __half g_tokT[8 * 1024 * 1024];      // [n][l][c]
__device__ __half g_wg[8 * 256 * 128];          // [g][r][k]
__device__ float  g_bg[8 * 256];
__device__ __half g_wfb[1024 * 1024];           // blocked+swizzled [cb8][kc16][m128][64h]
__device__ float  g_bf[1024];

// ---------------- helpers ----------------
__device__ __forceinline__ uint32_t smem_u32(const void* p) {
    uint32_t a;
    asm("{ .reg .u64 t; cvta.to.shared.u64 t, %1; cvt.u32.u64 %0, t; }" : "=r"(a) : "l"(p));
    return a;
}
#define CPA(dst, src) asm volatile("cp.async.cg.shared.global [%0], [%1], 16;" :: "r"(dst), "l"(__cvta_generic_to_global(src)))
#define CPC()  asm volatile("cp.async.commit_group;" ::: "memory")
#define CPW0() asm volatile("cp.async.wait_group 0;" ::: "memory")
#define CPW1() asm volatile("cp.async.wait_group 1;" ::: "memory")
#define LDSM4(r0, r1, r2, r3, a) \
    asm volatile("ldmatrix.sync.aligned.m8n8.x4.shared.b16 {%0,%1,%2,%3}, [%4];" \
        : "=r"(r0), "=r"(r1), "=r"(r2), "=r"(r3) : "r"(a))

#define MBAR_INIT(a, c) asm volatile("mbarrier.init.shared.b64 [%0], %1;" :: "r"(a), "r"(c) : "memory")
#define MBAR_EXPECT(a, bytes) \
    asm volatile("mbarrier.arrive.expect_tx.shared.b64 _, [%0], %1;" :: "r"(a), "r"(bytes) : "memory")
#define CPBULK(dstS, srcG, bytes, mbar) \
    asm volatile("cp.async.bulk.shared::cta.global.mbarrier::complete_tx::bytes [%0], [%1], %2, [%3];" \
        :: "r"(dstS), "l"(__cvta_generic_to_global(srcG)), "r"(bytes), "r"(mbar) : "memory")
#define MBAR_WAIT(mbar_addr, parity) do { \
    uint32_t _m = (mbar_addr), _p = (parity), _d; \
    asm volatile("{\n\t.reg .pred p;\n\t" \
        "mbarrier.try_wait.parity.acquire.cta.shared::cta.b64 p, [%1], %2;\n\t" \
        "selp.b32 %0, 1, 0, p;\n\t}" : "=r"(_d) : "r"(_m), "r"(_p) : "memory"); \
    if (!_d) { \
        asm volatile("{\n\t.reg .pred P1;\n\t" \
            "WL_%=:\n\t" \
            "mbarrier.try_wait.parity.acquire.cta.shared::cta.b64 P1, [%0], %1, 0x989680;\n\t" \
            "@P1 bra.uni WD_%=;\n\t" \
            "bra.uni WL_%=;\n\t" \
            "WD_%=:\n\t}" :: "r"(_m), "r"(_p) : "memory"); \
    } \
} while (0)

__device__ __forceinline__ void mma16(float* d, const uint32_t* a, uint32_t b0, uint32_t b1) {
    asm volatile(
        "mma.sync.aligned.m16n8k16.row.col.f32.f16.f16.f32 "
        "{%0,%1,%2,%3}, {%4,%5,%6,%7}, {%8,%9}, {%0,%1,%2,%3};"
        : "+f"(d[0]), "+f"(d[1]), "+f"(d[2]), "+f"(d[3])
        : "r"(a[0]), "r"(a[1]), "r"(a[2]), "r"(a[3]), "r"(b0), "r"(b1));
}
__device__ __forceinline__ uint32_t packh2(float a, float b) {
    __half2 h = __floats2half2_rn(a, b);
    return *(uint32_t*)&h;
}
__device__ __forceinline__ float ex2f(float x) {
    float r;
    asm("ex2.approx.f32 %0, %1;" : "=f"(r) : "f"(x));
    return r;
}
#define L2E 1.4426950408889634f

// ---------------- fused prep + tokens transpose ----------------
#define TRANS_BLOCKS 8192
__global__ __launch_bounds__(256) void prep_kernel(
    const float* __restrict__ tokens,
    const float* __restrict__ kw, const float* __restrict__ kb, const float* __restrict__ kga,
    const float* __restrict__ kbe, const float* __restrict__ km, const float* __restrict__ kv,
    const float* __restrict__ qw, const float* __restrict__ qb, const float* __restrict__ qga,
    const float* __restrict__ qbe, const float* __restrict__ qm, const float* __restrict__ qv,
    const float* __restrict__ vw, const float* __restrict__ vb, const float* __restrict__ vga,
    const float* __restrict__ vbe, const float* __restrict__ vm, const float* __restrict__ vv,
    const float* __restrict__ fw, const float* __restrict__ fb, const float* __restrict__ fga,
    const float* __restrict__ fbe, const float* __restrict__ fm, const float* __restrict__ fv)
{
    __shared__ float tile[32][33];
    int t = threadIdx.x;
    if (blockIdx.x < TRANS_BLOCKS) {
        int bid = blockIdx.x;
        int l0 = (bid & 31) * 32, c0 = ((bid >> 5) & 31) * 32, n = bid >> 10;
#pragma unroll
        for (int i = 0; i < 4; ++i) {
            int idx = i * 256 + t;
            int r = idx >> 5, col = idx & 31;
            tile[r][col] = tokens[((size_t)(n * 1024 + c0 + r)) * 1024 + l0 + col];
        }
        __syncthreads();
#pragma unroll
        for (int i = 0; i < 4; ++i) {
            int idx = i * 256 + t;
            int r = idx >> 5, col = idx & 31;
            g_tokT[((size_t)(n * 1024 + l0 + r)) * 1024 + c0 + col] = __float2half(tile[col][r]);
        }
        return;
    }
    int id = (blockIdx.x - TRANS_BLOCKS) * 256 + t;
    if (id < 1024 * 1024) {
        int k = id & 1023, c = id >> 10;
        float inv = fga[c] * rsqrtf(fv[c] + 1e-5f);
        int cb = c >> 7, m = c & 127, kc = k >> 6, ch = (k >> 3) & 7, w = k & 7;
        size_t dst = ((size_t)((cb * 16 + kc) * 128 + m)) * 64 + ((ch ^ (m & 7)) << 3) + w;
        g_wfb[dst] = __float2half(fw[id] * inv);
        return;
    }
    int id2 = id - 1024 * 1024;
    if (id2 < 8 * 256 * 128) {
        int k = id2 & 127;
        int r = (id2 >> 7) & 255;
        int g = id2 >> 15;
        float w;
        if (r < 64) {
            int c = g * 64 + r;
            float inv = kga[c] * rsqrtf(kv[c] + 1e-5f);
            w = kw[c * 128 + k] * inv;
        } else if (r < 128) {
            int c = g * 64 + (r - 64);
            float inv = qga[c] * rsqrtf(qv[c] + 1e-5f);
            w = qw[c * 128 + k] * inv * (0.03125f * L2E);   // fold 1/sqrt(L) and log2e
        } else {
            int c = g * 128 + (r - 128);
            float inv = vga[c] * rsqrtf(vv[c] + 1e-5f);
            w = vw[c * 128 + k] * inv;
        }
        g_wg[id2] = __float2half(w);
        return;
    }
    int id3 = id2 - 8 * 256 * 128;
    if (id3 < 8 * 256) {
        int g = id3 >> 8, r = id3 & 255;
        float bias;
        if (r < 64) {
            int c = g * 64 + r;
            float inv = kga[c] * rsqrtf(kv[c] + 1e-5f);
            bias = kb[c] * inv + kbe[c] - km[c] * inv;
        } else if (r < 128) {
            int c = g * 64 + (r - 64);
            float inv = qga[c] * rsqrtf(qv[c] + 1e-5f);
            bias = (qb[c] * inv + qbe[c] - qm[c] * inv) * (0.03125f * L2E);
        } else {
            int c = g * 128 + (r - 128);
            float inv = vga[c] * rsqrtf(vv[c] + 1e-5f);
            bias = vb[c] * inv + vbe[c] - vm[c] * inv;
        }
        g_bg[id3] = bias;
        return;
    }
    int c = id3 - 8 * 256;
    if (c < 1024) {
        float inv = fga[c] * rsqrtf(fv[c] + 1e-5f);
        g_bf[c] = fb[c] * inv + fbe[c] - fm[c] * inv;
    }
}

// ---------------- GEMM pieces (fp16, ldmatrix, K-chunk 64, padded pitch) ----------------
#define TP64 144u
#define GTILE 18432u
#define GSTG  36864u
#define GEMM_SMEM 110592
__device__ __forceinline__ void load_tile64(uint32_t dst, const __half* src, int stride_h, int t)
{
#pragma unroll
    for (int i = 0; i < 4; ++i) {
        int idx = i * 256 + t;
        int row = idx >> 3, c16 = idx & 7;
        CPA(dst + (uint32_t)row * TP64 + (uint32_t)c16 * 16u, src + (size_t)row * stride_h + c16 * 8);
    }
}

__device__ __forceinline__ void wgemm64(uint32_t As, uint32_t Bs, float C[4][4][4], int lane,
                                        int m0, int n0)
{
    int lr = (lane & 7) + ((lane >> 3) & 1) * 8;
    int akb = ((lane >> 4) & 1) * 8;
    int br = (lane & 7) + ((lane >> 4) & 1) * 8;
    int bkb = ((lane >> 3) & 1) * 8;
#pragma unroll
    for (int ks = 0; ks < 4; ++ks) {
        uint32_t a[4][4];
#pragma unroll
        for (int mi = 0; mi < 4; ++mi)
            LDSM4(a[mi][0], a[mi][1], a[mi][2], a[mi][3],
                  As + (uint32_t)(m0 + mi * 16 + lr) * TP64 + (uint32_t)((ks * 16 + akb) * 2));
#pragma unroll
        for (int np = 0; np < 2; ++np) {
            uint32_t b0, b1, b2, b3;
            LDSM4(b0, b1, b2, b3,
                  Bs + (uint32_t)(n0 + np * 16 + br) * TP64 + (uint32_t)((ks * 16 + bkb) * 2));
#pragma unroll
            for (int mi = 0; mi < 4; ++mi) {
                mma16(C[mi][np * 2], a[mi], b0, b1);
                mma16(C[mi][np * 2 + 1], a[mi], b2, b3);
            }
        }
    }
}

// ---------------- qkv conv GEMM (unchanged) ----------------
__global__ __launch_bounds__(256, 2) void qkv_tc()
{
    extern __shared__ float sm[];
    uint32_t sb = smem_u32(sm);
    int t = threadIdx.x, wid = t >> 5, lane = t & 31;
    int lt = blockIdx.x, rb = blockIdx.y, ng = blockIdx.z;
    int n = ng >> 3, g = ng & 7;
    int l0 = lt * 128;
    int m0 = (wid & 1) * 64, n0 = (wid >> 1) * 32;
    const __half* Ag = g_wg + (size_t)(g * 256 + rb * 128) * 128;
    const __half* Bg = g_tokT + ((size_t)(n * 1024 + l0)) * 1024 + g * 128;

    float C[4][4][4] = {};
    load_tile64(sb, Ag, 128, t);
    load_tile64(sb + GTILE, Bg, 1024, t);
    CPC();
    load_tile64(sb + GSTG, Ag + 64, 128, t);
    load_tile64(sb + GSTG + GTILE, Bg + 64, 1024, t);
    CPC();
    for (int c = 0; c < 2; ++c) {
        if (c == 0) CPW1(); else CPW0();
        __syncthreads();
        uint32_t As = sb + (uint32_t)c * GSTG;
        wgemm64(As, As + GTILE, C, lane, m0, n0);
    }
    __syncthreads();

    float* Sb = sm;  // [128][33]
    int r4 = lane >> 2, j = lane & 3;
    for (int ch = 0; ch < 4; ++ch) {
        if ((wid >> 1) == ch) {
#pragma unroll
            for (int mi = 0; mi < 4; ++mi)
#pragma unroll
                for (int ni = 0; ni < 4; ++ni) {
                    int m = m0 + mi * 16 + r4;
                    int q = ni * 8 + 2 * j;
                    Sb[m * 33 + q] = C[mi][ni][0];
                    Sb[m * 33 + q + 1] = C[mi][ni][1];
                    Sb[(m + 8) * 33 + q] = C[mi][ni][2];
                    Sb[(m + 8) * 33 + q + 1] = C[mi][ni][3];
                }
        }
        __syncthreads();
        if (rb == 0) {
#pragma unroll
            for (int i = 0; i < 8; ++i) {
                int m = t & 63, l = (t >> 6) + 4 * i;
                int h = 2 * g + (m >> 5), d = m & 31;
                size_t base = (((size_t)(n * 16 + h)) * 1024 + l0 + ch * 32 + l) * 32 + d;
                g_kbuf[base] = __float2half(Sb[m * 33 + l] + g_bg[g * 256 + m]);
                g_qbuf[base] = __float2half(Sb[(m + 64) * 33 + l] + g_bg[g * 256 + 64 + m]);
            }
        } else {
#pragma unroll
            for (int i = 0; i < 16; ++i) {
                int l = t & 31, m = (t >> 5) + 8 * i;
                g_vbuf[((size_t)(n * 1024 + g * 128 + m)) * 1024 + l0 + ch * 32 + l] =
                    __float2half(Sb[m * 33 + l] + g_bg[g * 256 + 128 + m]);
            }
        }
        __syncthreads();
    }
}

// ---------------- ff conv: 64x128 tile, 512 thr, 2 CTAs/SM, bulk 4-stage (R13) ----------------
#define FA2 8192u
#define FB2 16384u
#define FSTG2 24576u
#define FCONV_SMEM 98304
#define SWA(row, ch) (((uint32_t)(row) << 7) + (uint32_t)(((ch) ^ ((row) & 7)) << 4))

__global__ __launch_bounds__(512, 2) void fconv_tc(float* __restrict__ out)
{
    extern __shared__ float sm[];
    uint32_t sb = smem_u32(sm);
    __shared__ __align__(8) uint64_t s_mbar[4];
    int t = threadIdx.x, wid = t >> 5, lane = t & 31;
    int lt = blockIdx.x, cb2 = blockIdx.y, n = blockIdx.z;
    int l0 = lt * 128;
    int cb = cb2 >> 1, mofs = (cb2 & 1) * 64;
    int m0 = (wid & 1) * 32, n0 = (wid >> 1) * 16;
    const __half* Ag = g_wfb + (size_t)(cb * 16) * 128 * 64 + (size_t)mofs * 64;
    const __half* Bg = g_t2b + (size_t)(n * 16) * 1024 * 64 + (size_t)l0 * 64;

    if (t == 0) {
#pragma unroll
        for (int s = 0; s < 4; ++s) MBAR_INIT(smem_u32(&s_mbar[s]), 1);
    }
    __syncthreads();
    if (t == 0) {
#pragma unroll
        for (int c = 0; c < 3; ++c) {
            uint32_t mb = smem_u32(&s_mbar[c]);
            MBAR_EXPECT(mb, FSTG2);
            CPBULK(sb + (uint32_t)c * FSTG2, Ag + (size_t)c * 8192, FA2, mb);
            CPBULK(sb + (uint32_t)c * FSTG2 + FA2, Bg + (size_t)c * 65536, FB2, mb);
        }
    }

    float C[2][2][4] = {};
    int lr = (lane & 7) + ((lane >> 3) & 1) * 8;
    int akb8 = (lane >> 4) & 1;
    int br = (lane & 7) + ((lane >> 4) & 1) * 8;
    int bkb8 = (lane >> 3) & 1;

    for (int c = 0; c < 16; ++c) {
        int st = c & 3;
        MBAR_WAIT(smem_u32(&s_mbar[st]), (c >> 2) & 1);
        __syncthreads();
        if (t == 0 && c + 3 < 16) {
            int nc = c + 3, ns = nc & 3;
            uint32_t mb = smem_u32(&s_mbar[ns]);
            MBAR_EXPECT(mb, FSTG2);
            CPBULK(sb + (uint32_t)ns * FSTG2, Ag + (size_t)nc * 8192, FA2, mb);
            CPBULK(sb + (uint32_t)ns * FSTG2 + FA2, Bg + (size_t)nc * 65536, FB2, mb);
        }
        uint32_t As = sb + (uint32_t)st * FSTG2;
        uint32_t Bs = As + FA2;
#pragma unroll
        for (int ks = 0; ks < 4; ++ks) {
            uint32_t a[2][4];
#pragma unroll
            for (int mi = 0; mi < 2; ++mi) {
                int row = m0 + mi * 16 + lr;
                LDSM4(a[mi][0], a[mi][1], a[mi][2], a[mi][3], As + SWA(row, ks * 2 + akb8));
            }
            uint32_t b0, b1, b2, b3;
            {
                int row = n0 + br;
                LDSM4(b0, b1, b2, b3, Bs + SWA(row, ks * 2 + bkb8));
            }
#pragma unroll
            for (int mi = 0; mi < 2; ++mi) {
                mma16(C[mi][0], a[mi], b0, b1);
                mma16(C[mi][1], a[mi], b2, b3);
            }
        }
    }
    __syncthreads();

    float* Ob = sm;   // [64][133] fp32
    int r4 = lane >> 2, j = lane & 3;
#pragma unroll
    for (int mi = 0; mi < 2; ++mi)
#pragma unroll
        for (int ni = 0; ni < 2; ++ni) {
            int m = m0 + mi * 16 + r4;
            int q = n0 + ni * 8 + 2 * j;
            Ob[m * 133 + q] = C[mi][ni][0];
            Ob[m * 133 + q + 1] = C[mi][ni][1];
            Ob[(m + 8) * 133 + q] = C[mi][ni][2];
            Ob[(m + 8) * 133 + q + 1] = C[mi][ni][3];
        }
    __syncthreads();
#pragma unroll
    for (int i = 0; i < 16; ++i) {
        int idx = i * 512 + t;
        int m = idx >> 7, l = idx & 127;
        size_t addr = ((size_t)(n * 1024 + cb2 * 64 + m)) * 1024 + l0 + l;
        out[addr] = Ob[m * 133 + l] + g_bf[cb2 * 64 + m] + g_t2[addr];
    }
}

// ---------------- flash attention: max-free softmax, 4-stage paired tiles ----------------
#define TPK 80u
#define KST 5120u
#define AST 14336u
#define ATTN_SMEM 57344

__device__ __forceinline__ void attn_load(uint32_t sb, const __half* Kg, const __half* Vg,
                                          int kt, int st, int t)
{
    uint32_t base = sb + (uint32_t)st * AST;
    int k0 = kt * 64;
    int row = t >> 2, c16 = t & 3;
    CPA(base + (uint32_t)row * TPK + (uint32_t)c16 * 16u, Kg + (size_t)(k0 + row) * 32 + c16 * 8);
#pragma unroll
    for (int i = 0; i < 2; ++i) {
        int idx = i * 256 + t;
        int vr = idx >> 3, vc = idx & 7;
        CPA(base + KST + (uint32_t)(vr * 144 + vc * 16), Vg + (size_t)vr * 1024 + k0 + vc * 8);
    }
    CPC();
}

__global__ __launch_bounds__(256, 2) void attn_tc(const float* __restrict__ tokens)
{
    extern __shared__ float sm[];
    uint32_t sb = smem_u32(sm);

    int t = threadIdx.x, wid = t >> 5, lane = t & 31;
    int r4 = lane >> 2, j = lane & 3;
    int qt = blockIdx.x, h = blockIdx.y, n = blockIdx.z;
    int q0g = qt * 128, q0w = wid * 16;
    const __half* Kg = g_kbuf + ((size_t)(n * 16 + h)) * 1024 * 32;
    const __half* Qg = g_qbuf + ((size_t)(n * 16 + h)) * 1024 * 32;
    const __half* Vg = g_vbuf + ((size_t)(n * 1024 + h * 64)) * 1024;

    uint32_t aq[2][4];
#pragma unroll
    for (int ds = 0; ds < 2; ++ds) {
        const __half* qb = Qg + (size_t)(q0g + q0w + r4) * 32 + ds * 16 + 2 * j;
        aq[ds][0] = *(const uint32_t*)qb;
        aq[ds][1] = *(const uint32_t*)(qb + 8 * 32);
        aq[ds][2] = *(const uint32_t*)(qb + 8);
        aq[ds][3] = *(const uint32_t*)(qb + 8 * 32 + 8);
    }

    attn_load(sb, Kg, Vg, 0, 0, t);
    attn_load(sb, Kg, Vg, 1, 1, t);

    float CO[8][4] = {};
    float l0 = 0.f, l1 = 0.f;
    int lr = (lane & 7) + ((lane >> 4) & 1) * 8;
    int kbo = ((lane >> 3) & 1) * 8;

    for (int pr = 0; pr < 8; ++pr) {
        CPW0();
        __syncthreads();
        if (pr < 7) {
            attn_load(sb, Kg, Vg, 2 * pr + 2, (2 * pr + 2) & 3, t);
            attn_load(sb, Kg, Vg, 2 * pr + 3, (2 * pr + 3) & 3, t);
        }
#pragma unroll
        for (int sub = 0; sub < 2; ++sub) {
            int kt = 2 * pr + sub;
            uint32_t ksm = sb + (uint32_t)(kt & 3) * AST;
            uint32_t vsm = ksm + KST;

            // ---- S = Q . K^T (S already in log2 domain) ----
            float CS[8][4] = {};
#pragma unroll
            for (int ds = 0; ds < 2; ++ds)
#pragma unroll
                for (int ntp = 0; ntp < 4; ++ntp) {
                    uint32_t b0, b1, b2, b3;
                    LDSM4(b0, b1, b2, b3,
                          ksm + (uint32_t)(ntp * 16 + lr) * TPK + (uint32_t)((ds * 16 + kbo) * 2));
                    mma16(CS[2 * ntp], aq[ds], b0, b1);
                    mma16(CS[2 * ntp + 1], aq[ds], b2, b3);
                }

            // ---- max-free softmax numerator: e = 2^S; thread-local partial sums ----
#pragma unroll
            for (int nt = 0; nt < 8; ++nt) {
                float e0 = ex2f(CS[nt][0]);
                float e1 = ex2f(CS[nt][1]);
                float e2 = ex2f(CS[nt][2]);
                float e3 = ex2f(CS[nt][3]);
                l0 += e0 + e1; l1 += e2 + e3;
                CS[nt][0] = e0; CS[nt][1] = e1; CS[nt][2] = e2; CS[nt][3] = e3;
            }

            // ---- O += P . V (no rescale needed) ----
#pragma unroll
            for (int kc = 0; kc < 4; ++kc) {
                uint32_t ap[4];
                ap[0] = packh2(CS[2 * kc][0], CS[2 * kc][1]);
                ap[1] = packh2(CS[2 * kc][2], CS[2 * kc][3]);
                ap[2] = packh2(CS[2 * kc + 1][0], CS[2 * kc + 1][1]);
                ap[3] = packh2(CS[2 * kc + 1][2], CS[2 * kc + 1][3]);
#pragma unroll
                for (int ntp = 0; ntp < 4; ++ntp) {
                    uint32_t b0, b1, b2, b3;
                    LDSM4(b0, b1, b2, b3,
                          vsm + (uint32_t)((ntp * 16 + lr) * 144 + (kc * 16 + kbo) * 2));
                    mma16(CO[2 * ntp], ap, b0, b1);
                    mma16(CO[2 * ntp + 1], ap, b2, b3);
                }
            }
        }
    }

    // ---- epilogue: reduce row sums once ----
    l0 += __shfl_xor_sync(0xffffffffu, l0, 1);
    l0 += __shfl_xor_sync(0xffffffffu, l0, 2);
    l1 += __shfl_xor_sync(0xffffffffu, l1, 1);
    l1 += __shfl_xor_sync(0xffffffffu, l1, 2);

    __syncthreads();
    float* Ob = sm;  // [64][133]
    float li0 = 1.0f / l0, li1 = 1.0f / l1;
#pragma unroll
    for (int nt = 0; nt < 8; ++nt) {
        int d = nt * 8 + 2 * j;
        int q = q0w + r4;
        Ob[d * 133 + q] = CO[nt][0] * li0;
        Ob[(d + 1) * 133 + q] = CO[nt][1] * li0;
        Ob[d * 133 + q + 8] = CO[nt][2] * li1;
        Ob[(d + 1) * 133 + q + 8] = CO[nt][3] * li1;
    }
    __syncthreads();
#pragma unroll
    for (int i = 0; i < 32; ++i) {
        int q = t & 127, d = (t >> 7) + 2 * i;
        size_t addr = ((size_t)(n * 1024 + h * 64 + d)) * 1024 + q0g + q;
        float r = tokens[addr] + Ob[d * 133 + q];
        g_t2[addr] = r;
        Ob[d * 133 + q] = r;
    }
    __syncthreads();
#pragma unroll
    for (int i = 0; i < 32; ++i) {
        int d = t & 63, l = (t >> 6) + 4 * i;
        int lg = q0g + l;
        size_t dst = ((size_t)(n * 16 + h) * 1024 + lg) * 64 + (((d >> 3) ^ (lg & 7)) << 3) + (d & 7);
        g_t2b[dst] = __float2half(Ob[d * 133 + l]);
    }
}

// ---------------- launch ----------------
extern "C" void kernel_launch(void* const* d_in, const int* in_sizes, int n_in,
                              void* d_out, int out_size)
{
    (void)in_sizes; (void)n_in; (void)out_size;
    const float* tokens = (const float*)d_in[0];
    const float* p[24];
    for (int i = 0; i < 24; ++i) p[i] = (const float*)d_in[1 + i];

    cudaFuncSetAttribute(qkv_tc, cudaFuncAttributeMaxDynamicSharedMemorySize, GEMM_SMEM);
    cudaFuncSetAttribute(fconv_tc, cudaFuncAttributeMaxDynamicSharedMemorySize, FCONV_SMEM);
    cudaFuncSetAttribute(attn_tc, cudaFuncAttributeMaxDynamicSharedMemorySize, ATTN_SMEM);

    int prep_blocks = TRANS_BLOCKS + (1024 * 1024 + 8 * 256 * 128 + 8 * 256 + 1024 + 255) / 256;
    prep_kernel<<<prep_blocks, 256>>>(tokens,
        p[0], p[1], p[2], p[3], p[4], p[5],
        p[6], p[7], p[8], p[9], p[10], p[11],
        p[12], p[13], p[14], p[15], p[16], p[17],
        p[18], p[19], p[20], p[21], p[22], p[23]);

    qkv_tc<<<dim3(8, 2, 64), 256, GEMM_SMEM>>>();
    attn_tc<<<dim3(8, 16, 8), 256, ATTN_SMEM>>>(tokens);
    fconv_tc<<<dim3(8, 16, 8), 512, FCONV_SMEM>>>((float*)d_out);
}

// round 15
// speedup vs baseline: 1.2272x; 1.0091x over previous
#include <cuda_runtime.h>
#include <cuda_fp16.h>
#include <cstdint>
#include <math.h>

// ---------------- scratch ----------------
__device__ __half g_kbuf[8 * 16 * 1024 * 32];   // [n][h][l][d]
__device__ __half g_qbuf[8 * 16 * 1024 * 32];   // [n][h][l][d] (pre-scaled log2e/32)
__device__ __half g_vbuf[8 * 1024 * 1024];      // [n][c][l]
__device__ float  g_t2 [8 * 1024 * 1024];       // [n][c][l] fp32 residual
__device__ __half g_t2b[8 * 1024 * 1024];       // blocked+swizzled [n][kc16][l][64h]
__device__ __half g_tokT[8 * 1024 * 1024];      // [n][l][c]
__device__ __half g_wg[8 * 256 * 128];          // [g][r][k]
__device__ float  g_bg[8 * 256];
__device__ __half g_wfb[1024 * 1024];           // blocked+swizzled [cb8][kc16][m128][64h]
__device__ float  g_bf[1024];

// ---------------- helpers ----------------
__device__ __forceinline__ uint32_t smem_u32(const void* p) {
    uint32_t a;
    asm("{ .reg .u64 t; cvta.to.shared.u64 t, %1; cvt.u32.u64 %0, t; }" : "=r"(a) : "l"(p));
    return a;
}
#define CPA(dst, src) asm volatile("cp.async.cg.shared.global [%0], [%1], 16;" :: "r"(dst), "l"(__cvta_generic_to_global(src)))
#define CPC()  asm volatile("cp.async.commit_group;" ::: "memory")
#define CPW0() asm volatile("cp.async.wait_group 0;" ::: "memory")
#define CPW1() asm volatile("cp.async.wait_group 1;" ::: "memory")
#define LDSM4(r0, r1, r2, r3, a) \
    asm volatile("ldmatrix.sync.aligned.m8n8.x4.shared.b16 {%0,%1,%2,%3}, [%4];" \
        : "=r"(r0), "=r"(r1), "=r"(r2), "=r"(r3) : "r"(a))

#define MBAR_INIT(a, c) asm volatile("mbarrier.init.shared.b64 [%0], %1;" :: "r"(a), "r"(c) : "memory")
#define MBAR_EXPECT(a, bytes) \
    asm volatile("mbarrier.arrive.expect_tx.shared.b64 _, [%0], %1;" :: "r"(a), "r"(bytes) : "memory")
#define CPBULK(dstS, srcG, bytes, mbar) \
    asm volatile("cp.async.bulk.shared::cta.global.mbarrier::complete_tx::bytes [%0], [%1], %2, [%3];" \
        :: "r"(dstS), "l"(__cvta_generic_to_global(srcG)), "r"(bytes), "r"(mbar) : "memory")
#define MBAR_WAIT(mbar_addr, parity) do { \
    uint32_t _m = (mbar_addr), _p = (parity), _d; \
    asm volatile("{\n\t.reg .pred p;\n\t" \
        "mbarrier.try_wait.parity.acquire.cta.shared::cta.b64 p, [%1], %2;\n\t" \
        "selp.b32 %0, 1, 0, p;\n\t}" : "=r"(_d) : "r"(_m), "r"(_p) : "memory"); \
    if (!_d) { \
        asm volatile("{\n\t.reg .pred P1;\n\t" \
            "WL_%=:\n\t" \
            "mbarrier.try_wait.parity.acquire.cta.shared::cta.b64 P1, [%0], %1, 0x989680;\n\t" \
            "@P1 bra.uni WD_%=;\n\t" \
            "bra.uni WL_%=;\n\t" \
            "WD_%=:\n\t}" :: "r"(_m), "r"(_p) : "memory"); \
    } \
} while (0)

__device__ __forceinline__ void mma16(float* d, const uint32_t* a, uint32_t b0, uint32_t b1) {
    asm volatile(
        "mma.sync.aligned.m16n8k16.row.col.f32.f16.f16.f32 "
        "{%0,%1,%2,%3}, {%4,%5,%6,%7}, {%8,%9}, {%0,%1,%2,%3};"
        : "+f"(d[0]), "+f"(d[1]), "+f"(d[2]), "+f"(d[3])
        : "r"(a[0]), "r"(a[1]), "r"(a[2]), "r"(a[3]), "r"(b0), "r"(b1));
}
__device__ __forceinline__ uint32_t packh2(float a, float b) {
    __half2 h = __floats2half2_rn(a, b);
    return *(uint32_t*)&h;
}
__device__ __forceinline__ float ex2f(float x) {
    float r;
    asm("ex2.approx.f32 %0, %1;" : "=f"(r) : "f"(x));
    return r;
}
#define L2E 1.4426950408889634f

// ---------------- fused prep + tokens transpose ----------------
#define TRANS_BLOCKS 8192
__global__ __launch_bounds__(256) void prep_kernel(
    const float* __restrict__ tokens,
    const float* __restrict__ kw, const float* __restrict__ kb, const float* __restrict__ kga,
    const float* __restrict__ kbe, const float* __restrict__ km, const float* __restrict__ kv,
    const float* __restrict__ qw, const float* __restrict__ qb, const float* __restrict__ qga,
    const float* __restrict__ qbe, const float* __restrict__ qm, const float* __restrict__ qv,
    const float* __restrict__ vw, const float* __restrict__ vb, const float* __restrict__ vga,
    const float* __restrict__ vbe, const float* __restrict__ vm, const float* __restrict__ vv,
    const float* __restrict__ fw, const float* __restrict__ fb, const float* __restrict__ fga,
    const float* __restrict__ fbe, const float* __restrict__ fm, const float* __restrict__ fv)
{
    __shared__ float tile[32][33];
    int t = threadIdx.x;
    if (blockIdx.x < TRANS_BLOCKS) {
        int bid = blockIdx.x;
        int l0 = (bid & 31) * 32, c0 = ((bid >> 5) & 31) * 32, n = bid >> 10;
#pragma unroll
        for (int i = 0; i < 4; ++i) {
            int idx = i * 256 + t;
            int r = idx >> 5, col = idx & 31;
            tile[r][col] = tokens[((size_t)(n * 1024 + c0 + r)) * 1024 + l0 + col];
        }
        __syncthreads();
#pragma unroll
        for (int i = 0; i < 4; ++i) {
            int idx = i * 256 + t;
            int r = idx >> 5, col = idx & 31;
            g_tokT[((size_t)(n * 1024 + l0 + r)) * 1024 + c0 + col] = __float2half(tile[col][r]);
        }
        return;
    }
    int id = (blockIdx.x - TRANS_BLOCKS) * 256 + t;
    if (id < 1024 * 1024) {
        int k = id & 1023, c = id >> 10;
        float inv = fga[c] * rsqrtf(fv[c] + 1e-5f);
        int cb = c >> 7, m = c & 127, kc = k >> 6, ch = (k >> 3) & 7, w = k & 7;
        size_t dst = ((size_t)((cb * 16 + kc) * 128 + m)) * 64 + ((ch ^ (m & 7)) << 3) + w;
        g_wfb[dst] = __float2half(fw[id] * inv);
        return;
    }
    int id2 = id - 1024 * 1024;
    if (id2 < 8 * 256 * 128) {
        int k = id2 & 127;
        int r = (id2 >> 7) & 255;
        int g = id2 >> 15;
        float w;
        if (r < 64) {
            int c = g * 64 + r;
            float inv = kga[c] * rsqrtf(kv[c] + 1e-5f);
            w = kw[c * 128 + k] * inv;
        } else if (r < 128) {
            int c = g * 64 + (r - 64);
            float inv = qga[c] * rsqrtf(qv[c] + 1e-5f);
            w = qw[c * 128 + k] * inv * (0.03125f * L2E);
        } else {
            int c = g * 128 + (r - 128);
            float inv = vga[c] * rsqrtf(vv[c] + 1e-5f);
            w = vw[c * 128 + k] * inv;
        }
        g_wg[id2] = __float2half(w);
        return;
    }
    int id3 = id2 - 8 * 256 * 128;
    if (id3 < 8 * 256) {
        int g = id3 >> 8, r = id3 & 255;
        float bias;
        if (r < 64) {
            int c = g * 64 + r;
            float inv = kga[c] * rsqrtf(kv[c] + 1e-5f);
            bias = kb[c] * inv + kbe[c] - km[c] * inv;
        } else if (r < 128) {
            int c = g * 64 + (r - 64);
            float inv = qga[c] * rsqrtf(qv[c] + 1e-5f);
            bias = (qb[c] * inv + qbe[c] - qm[c] * inv) * (0.03125f * L2E);
        } else {
            int c = g * 128 + (r - 128);
            float inv = vga[c] * rsqrtf(vv[c] + 1e-5f);
            bias = vb[c] * inv + vbe[c] - vm[c] * inv;
        }
        g_bg[id3] = bias;
        return;
    }
    int c = id3 - 8 * 256;
    if (c < 1024) {
        float inv = fga[c] * rsqrtf(fv[c] + 1e-5f);
        g_bf[c] = fb[c] * inv + fbe[c] - fm[c] * inv;
    }
}

// ---------------- GEMM pieces (fp16, ldmatrix, K-chunk 64, padded pitch) ----------------
#define TP64 144u
#define GTILE 18432u
#define GSTG  36864u
#define GEMM_SMEM 110592
__device__ __forceinline__ void load_tile64(uint32_t dst, const __half* src, int stride_h, int t)
{
#pragma unroll
    for (int i = 0; i < 4; ++i) {
        int idx = i * 256 + t;
        int row = idx >> 3, c16 = idx & 7;
        CPA(dst + (uint32_t)row * TP64 + (uint32_t)c16 * 16u, src + (size_t)row * stride_h + c16 * 8);
    }
}

__device__ __forceinline__ void wgemm64(uint32_t As, uint32_t Bs, float C[4][4][4], int lane,
                                        int m0, int n0)
{
    int lr = (lane & 7) + ((lane >> 3) & 1) * 8;
    int akb = ((lane >> 4) & 1) * 8;
    int br = (lane & 7) + ((lane >> 4) & 1) * 8;
    int bkb = ((lane >> 3) & 1) * 8;
#pragma unroll
    for (int ks = 0; ks < 4; ++ks) {
        uint32_t a[4][4];
#pragma unroll
        for (int mi = 0; mi < 4; ++mi)
            LDSM4(a[mi][0], a[mi][1], a[mi][2], a[mi][3],
                  As + (uint32_t)(m0 + mi * 16 + lr) * TP64 + (uint32_t)((ks * 16 + akb) * 2));
#pragma unroll
        for (int np = 0; np < 2; ++np) {
            uint32_t b0, b1, b2, b3;
            LDSM4(b0, b1, b2, b3,
                  Bs + (uint32_t)(n0 + np * 16 + br) * TP64 + (uint32_t)((ks * 16 + bkb) * 2));
#pragma unroll
            for (int mi = 0; mi < 4; ++mi) {
                mma16(C[mi][np * 2], a[mi], b0, b1);
                mma16(C[mi][np * 2 + 1], a[mi], b2, b3);
            }
        }
    }
}

// ---------------- qkv conv GEMM (unchanged) ----------------
__global__ __launch_bounds__(256, 2) void qkv_tc()
{
    extern __shared__ float sm[];
    uint32_t sb = smem_u32(sm);
    int t = threadIdx.x, wid = t >> 5, lane = t & 31;
    int lt = blockIdx.x, rb = blockIdx.y, ng = blockIdx.z;
    int n = ng >> 3, g = ng & 7;
    int l0 = lt * 128;
    int m0 = (wid & 1) * 64, n0 = (wid >> 1) * 32;
    const __half* Ag = g_wg + (size_t)(g * 256 + rb * 128) * 128;
    const __half* Bg = g_tokT + ((size_t)(n * 1024 + l0)) * 1024 + g * 128;

    float C[4][4][4] = {};
    load_tile64(sb, Ag, 128, t);
    load_tile64(sb + GTILE, Bg, 1024, t);
    CPC();
    load_tile64(sb + GSTG, Ag + 64, 128, t);
    load_tile64(sb + GSTG + GTILE, Bg + 64, 1024, t);
    CPC();
    for (int c = 0; c < 2; ++c) {
        if (c == 0) CPW1(); else CPW0();
        __syncthreads();
        uint32_t As = sb + (uint32_t)c * GSTG;
        wgemm64(As, As + GTILE, C, lane, m0, n0);
    }
    __syncthreads();

    float* Sb = sm;  // [128][33]
    int r4 = lane >> 2, j = lane & 3;
    for (int ch = 0; ch < 4; ++ch) {
        if ((wid >> 1) == ch) {
#pragma unroll
            for (int mi = 0; mi < 4; ++mi)
#pragma unroll
                for (int ni = 0; ni < 4; ++ni) {
                    int m = m0 + mi * 16 + r4;
                    int q = ni * 8 + 2 * j;
                    Sb[m * 33 + q] = C[mi][ni][0];
                    Sb[m * 33 + q + 1] = C[mi][ni][1];
                    Sb[(m + 8) * 33 + q] = C[mi][ni][2];
                    Sb[(m + 8) * 33 + q + 1] = C[mi][ni][3];
                }
        }
        __syncthreads();
        if (rb == 0) {
#pragma unroll
            for (int i = 0; i < 8; ++i) {
                int m = t & 63, l = (t >> 6) + 4 * i;
                int h = 2 * g + (m >> 5), d = m & 31;
                size_t base = (((size_t)(n * 16 + h)) * 1024 + l0 + ch * 32 + l) * 32 + d;
                g_kbuf[base] = __float2half(Sb[m * 33 + l] + g_bg[g * 256 + m]);
                g_qbuf[base] = __float2half(Sb[(m + 64) * 33 + l] + g_bg[g * 256 + 64 + m]);
            }
        } else {
#pragma unroll
            for (int i = 0; i < 16; ++i) {
                int l = t & 31, m = (t >> 5) + 8 * i;
                g_vbuf[((size_t)(n * 1024 + g * 128 + m)) * 1024 + l0 + ch * 32 + l] =
                    __float2half(Sb[m * 33 + l] + g_bg[g * 256 + 128 + m]);
            }
        }
        __syncthreads();
    }
}

// ---------------- ff conv: 128x128 tile, 512 thr (16 warps 4x4), bulk 3-stage ----------------
#define FA3 16384u
#define FSTG3 32768u
#define FCONV_SMEM 98304
#define SWA(row, ch) (((uint32_t)(row) << 7) + (uint32_t)(((ch) ^ ((row) & 7)) << 4))

__global__ __launch_bounds__(512, 2) void fconv_tc(float* __restrict__ out)
{
    extern __shared__ float sm[];
    uint32_t sb = smem_u32(sm);
    __shared__ __align__(8) uint64_t s_mbar[3];
    int t = threadIdx.x, wid = t >> 5, lane = t & 31;
    int lt = blockIdx.x, cb = blockIdx.y, n = blockIdx.z;
    int l0 = lt * 128;
    int m0 = (wid & 3) * 32, n0 = (wid >> 2) * 32;
    const __half* Ag = g_wfb + (size_t)(cb * 16) * 128 * 64;           // chunk c: + c*8192 halves
    const __half* Bg = g_t2b + (size_t)(n * 16) * 1024 * 64 + (size_t)l0 * 64;  // chunk c: + c*65536 halves

    if (t == 0) {
#pragma unroll
        for (int s = 0; s < 3; ++s) MBAR_INIT(smem_u32(&s_mbar[s]), 1);
    }
    __syncthreads();
    if (t == 0) {
#pragma unroll
        for (int c = 0; c < 2; ++c) {
            uint32_t mb = smem_u32(&s_mbar[c]);
            MBAR_EXPECT(mb, FSTG3);
            CPBULK(sb + (uint32_t)c * FSTG3, Ag + (size_t)c * 8192, FA3, mb);
            CPBULK(sb + (uint32_t)c * FSTG3 + FA3, Bg + (size_t)c * 65536, FA3, mb);
        }
    }

    float C[2][4][4] = {};
    int lr = (lane & 7) + ((lane >> 3) & 1) * 8;
    int akb8 = (lane >> 4) & 1;
    int br = (lane & 7) + ((lane >> 4) & 1) * 8;
    int bkb8 = (lane >> 3) & 1;

    for (int c = 0; c < 16; ++c) {
        int st = c % 3;
        MBAR_WAIT(smem_u32(&s_mbar[st]), (c / 3) & 1);
        __syncthreads();
        if (t == 0 && c + 2 < 16) {
            int nc = c + 2, ns = nc % 3;
            uint32_t mb = smem_u32(&s_mbar[ns]);
            MBAR_EXPECT(mb, FSTG3);
            CPBULK(sb + (uint32_t)ns * FSTG3, Ag + (size_t)nc * 8192, FA3, mb);
            CPBULK(sb + (uint32_t)ns * FSTG3 + FA3, Bg + (size_t)nc * 65536, FA3, mb);
        }
        uint32_t As = sb + (uint32_t)st * FSTG3;
        uint32_t Bs = As + FA3;
#pragma unroll
        for (int ks = 0; ks < 4; ++ks) {
            uint32_t a[2][4];
#pragma unroll
            for (int mi = 0; mi < 2; ++mi) {
                int row = m0 + mi * 16 + lr;
                LDSM4(a[mi][0], a[mi][1], a[mi][2], a[mi][3], As + SWA(row, ks * 2 + akb8));
            }
#pragma unroll
            for (int np = 0; np < 2; ++np) {
                int row = n0 + np * 16 + br;
                uint32_t b0, b1, b2, b3;
                LDSM4(b0, b1, b2, b3, Bs + SWA(row, ks * 2 + bkb8));
#pragma unroll
                for (int mi = 0; mi < 2; ++mi) {
                    mma16(C[mi][np * 2], a[mi], b0, b1);
                    mma16(C[mi][np * 2 + 1], a[mi], b2, b3);
                }
            }
        }
    }
    __syncthreads();

    // one-pass epilogue: full 128x128 tile in smem (128*133*4 = 68KB <= 96KB)
    float* Ob = sm;
    int r4 = lane >> 2, j = lane & 3;
#pragma unroll
    for (int mi = 0; mi < 2; ++mi)
#pragma unroll
        for (int ni = 0; ni < 4; ++ni) {
            int m = m0 + mi * 16 + r4;
            int q = n0 + ni * 8 + 2 * j;
            Ob[m * 133 + q] = C[mi][ni][0];
            Ob[m * 133 + q + 1] = C[mi][ni][1];
            Ob[(m + 8) * 133 + q] = C[mi][ni][2];
            Ob[(m + 8) * 133 + q + 1] = C[mi][ni][3];
        }
    __syncthreads();
#pragma unroll
    for (int i = 0; i < 32; ++i) {
        int idx = i * 512 + t;
        int m = idx >> 7, l = idx & 127;
        size_t addr = ((size_t)(n * 1024 + cb * 128 + m)) * 1024 + l0 + l;
        out[addr] = Ob[m * 133 + l] + g_bf[cb * 128 + m] + g_t2[addr];
    }
}

// ---------------- flash attention: max-free softmax, 4-stage paired tiles ----------------
#define TPK 80u
#define KST 5120u
#define AST 14336u
#define ATTN_SMEM 57344

__device__ __forceinline__ void attn_load(uint32_t sb, const __half* Kg, const __half* Vg,
                                          int kt, int st, int t)
{
    uint32_t base = sb + (uint32_t)st * AST;
    int k0 = kt * 64;
    int row = t >> 2, c16 = t & 3;
    CPA(base + (uint32_t)row * TPK + (uint32_t)c16 * 16u, Kg + (size_t)(k0 + row) * 32 + c16 * 8);
#pragma unroll
    for (int i = 0; i < 2; ++i) {
        int idx = i * 256 + t;
        int vr = idx >> 3, vc = idx & 7;
        CPA(base + KST + (uint32_t)(vr * 144 + vc * 16), Vg + (size_t)vr * 1024 + k0 + vc * 8);
    }
    CPC();
}

__global__ __launch_bounds__(256, 2) void attn_tc(const float* __restrict__ tokens)
{
    extern __shared__ float sm[];
    uint32_t sb = smem_u32(sm);

    int t = threadIdx.x, wid = t >> 5, lane = t & 31;
    int r4 = lane >> 2, j = lane & 3;
    int qt = blockIdx.x, h = blockIdx.y, n = blockIdx.z;
    int q0g = qt * 128, q0w = wid * 16;
    const __half* Kg = g_kbuf + ((size_t)(n * 16 + h)) * 1024 * 32;
    const __half* Qg = g_qbuf + ((size_t)(n * 16 + h)) * 1024 * 32;
    const __half* Vg = g_vbuf + ((size_t)(n * 1024 + h * 64)) * 1024;

    uint32_t aq[2][4];
#pragma unroll
    for (int ds = 0; ds < 2; ++ds) {
        const __half* qb = Qg + (size_t)(q0g + q0w + r4) * 32 + ds * 16 + 2 * j;
        aq[ds][0] = *(const uint32_t*)qb;
        aq[ds][1] = *(const uint32_t*)(qb + 8 * 32);
        aq[ds][2] = *(const uint32_t*)(qb + 8);
        aq[ds][3] = *(const uint32_t*)(qb + 8 * 32 + 8);
    }

    attn_load(sb, Kg, Vg, 0, 0, t);
    attn_load(sb, Kg, Vg, 1, 1, t);

    float CO[8][4] = {};
    float l0 = 0.f, l1 = 0.f;
    int lr = (lane & 7) + ((lane >> 4) & 1) * 8;
    int kbo = ((lane >> 3) & 1) * 8;

    for (int pr = 0; pr < 8; ++pr) {
        CPW0();
        __syncthreads();
        if (pr < 7) {
            attn_load(sb, Kg, Vg, 2 * pr + 2, (2 * pr + 2) & 3, t);
            attn_load(sb, Kg, Vg, 2 * pr + 3, (2 * pr + 3) & 3, t);
        }
#pragma unroll
        for (int sub = 0; sub < 2; ++sub) {
            int kt = 2 * pr + sub;
            uint32_t ksm = sb + (uint32_t)(kt & 3) * AST;
            uint32_t vsm = ksm + KST;

            float CS[8][4] = {};
#pragma unroll
            for (int ds = 0; ds < 2; ++ds)
#pragma unroll
                for (int ntp = 0; ntp < 4; ++ntp) {
                    uint32_t b0, b1, b2, b3;
                    LDSM4(b0, b1, b2, b3,
                          ksm + (uint32_t)(ntp * 16 + lr) * TPK + (uint32_t)((ds * 16 + kbo) * 2));
                    mma16(CS[2 * ntp], aq[ds], b0, b1);
                    mma16(CS[2 * ntp + 1], aq[ds], b2, b3);
                }

#pragma unroll
            for (int nt = 0; nt < 8; ++nt) {
                float e0 = ex2f(CS[nt][0]);
                float e1 = ex2f(CS[nt][1]);
                float e2 = ex2f(CS[nt][2]);
                float e3 = ex2f(CS[nt][3]);
                l0 += e0 + e1; l1 += e2 + e3;
                CS[nt][0] = e0; CS[nt][1] = e1; CS[nt][2] = e2; CS[nt][3] = e3;
            }

#pragma unroll
            for (int kc = 0; kc < 4; ++kc) {
                uint32_t ap[4];
                ap[0] = packh2(CS[2 * kc][0], CS[2 * kc][1]);
                ap[1] = packh2(CS[2 * kc][2], CS[2 * kc][3]);
                ap[2] = packh2(CS[2 * kc + 1][0], CS[2 * kc + 1][1]);
                ap[3] = packh2(CS[2 * kc + 1][2], CS[2 * kc + 1][3]);
#pragma unroll
                for (int ntp = 0; ntp < 4; ++ntp) {
                    uint32_t b0, b1, b2, b3;
                    LDSM4(b0, b1, b2, b3,
                          vsm + (uint32_t)((ntp * 16 + lr) * 144 + (kc * 16 + kbo) * 2));
                    mma16(CO[2 * ntp], ap, b0, b1);
                    mma16(CO[2 * ntp + 1], ap, b2, b3);
                }
            }
        }
    }

    l0 += __shfl_xor_sync(0xffffffffu, l0, 1);
    l0 += __shfl_xor_sync(0xffffffffu, l0, 2);
    l1 += __shfl_xor_sync(0xffffffffu, l1, 1);
    l1 += __shfl_xor_sync(0xffffffffu, l1, 2);

    __syncthreads();
    float* Ob = sm;  // [64][133]
    float li0 = 1.0f / l0, li1 = 1.0f / l1;
#pragma unroll
    for (int nt = 0; nt < 8; ++nt) {
        int d = nt * 8 + 2 * j;
        int q = q0w + r4;
        Ob[d * 133 + q] = CO[nt][0] * li0;
        Ob[(d + 1) * 133 + q] = CO[nt][1] * li0;
        Ob[d * 133 + q + 8] = CO[nt][2] * li1;
        Ob[(d + 1) * 133 + q + 8] = CO[nt][3] * li1;
    }
    __syncthreads();
#pragma unroll
    for (int i = 0; i < 32; ++i) {
        int q = t & 127, d = (t >> 7) + 2 * i;
        size_t addr = ((size_t)(n * 1024 + h * 64 + d)) * 1024 + q0g + q;
        float r = tokens[addr] + Ob[d * 133 + q];
        g_t2[addr] = r;
        Ob[d * 133 + q] = r;
    }
    __syncthreads();
#pragma unroll
    for (int i = 0; i < 32; ++i) {
        int d = t & 63, l = (t >> 6) + 4 * i;
        int lg = q0g + l;
        size_t dst = ((size_t)(n * 16 + h) * 1024 + lg) * 64 + (((d >> 3) ^ (lg & 7)) << 3) + (d & 7);
        g_t2b[dst] = __float2half(Ob[d * 133 + l]);
    }
}

// ---------------- launch ----------------
extern "C" void kernel_launch(void* const* d_in, const int* in_sizes, int n_in,
                              void* d_out, int out_size)
{
    (void)in_sizes; (void)n_in; (void)out_size;
    const float* tokens = (const float*)d_in[0];
    const float* p[24];
    for (int i = 0; i < 24; ++i) p[i] = (const float*)d_in[1 + i];

    cudaFuncSetAttribute(qkv_tc, cudaFuncAttributeMaxDynamicSharedMemorySize, GEMM_SMEM);
    cudaFuncSetAttribute(fconv_tc, cudaFuncAttributeMaxDynamicSharedMemorySize, FCONV_SMEM);
    cudaFuncSetAttribute(attn_tc, cudaFuncAttributeMaxDynamicSharedMemorySize, ATTN_SMEM);

    int prep_blocks = TRANS_BLOCKS + (1024 * 1024 + 8 * 256 * 128 + 8 * 256 + 1024 + 255) / 256;
    prep_kernel<<<prep_blocks, 256>>>(tokens,
        p[0], p[1], p[2], p[3], p[4], p[5],
        p[6], p[7], p[8], p[9], p[10], p[11],
        p[12], p[13], p[14], p[15], p[16], p[17],
        p[18], p[19], p[20], p[21], p[22], p[23]);

    qkv_tc<<<dim3(8, 2, 64), 256, GEMM_SMEM>>>();
    attn_tc<<<dim3(8, 16, 8), 256, ATTN_SMEM>>>(tokens);
    fconv_tc<<<dim3(8, 8, 8), 512, FCONV_SMEM>>>((float*)d_out);
}

// round 16
// speedup vs baseline: 1.2868x; 1.0485x over previous
#include <cuda_runtime.h>
#include <cuda_fp16.h>
#include <cstdint>
#include <math.h>

// ---------------- scratch ----------------
__device__ __half g_kbuf[8 * 16 * 1024 * 32];   // [n][h][l][d]
__device__ __half g_qbuf[8 * 16 * 1024 * 32];   // [n][h][l][d] (pre-scaled log2e/32)
__device__ __half g_vbuf[8 * 1024 * 1024];      // [n][c][l]
__device__ float  g_t2 [8 * 1024 * 1024];       // [n][c][l] fp32 residual
__device__ __half g_t2b[8 * 1024 * 1024];       // blocked+swizzled [n][kc16][l][64h]
__device__ __half g_tokT[8 * 1024 * 1024];      // [n][l][c]
__device__ __half g_wg[8 * 256 * 128];          // [g][r][k]
__device__ float  g_bg[8 * 256];
__device__ __half g_wfb[1024 * 1024];           // blocked+swizzled [cb8][kc16][m128][64h]
__device__ float  g_bf[1024];

// ---------------- helpers ----------------
__device__ __forceinline__ uint32_t smem_u32(const void* p) {
    uint32_t a;
    asm("{ .reg .u64 t; cvta.to.shared.u64 t, %1; cvt.u32.u64 %0, t; }" : "=r"(a) : "l"(p));
    return a;
}
#define CPA(dst, src) asm volatile("cp.async.cg.shared.global [%0], [%1], 16;" :: "r"(dst), "l"(__cvta_generic_to_global(src)))
#define CPC()  asm volatile("cp.async.commit_group;" ::: "memory")
#define CPW0() asm volatile("cp.async.wait_group 0;" ::: "memory")
#define CPW1() asm volatile("cp.async.wait_group 1;" ::: "memory")
#define LDSM4(r0, r1, r2, r3, a) \
    asm volatile("ldmatrix.sync.aligned.m8n8.x4.shared.b16 {%0,%1,%2,%3}, [%4];" \
        : "=r"(r0), "=r"(r1), "=r"(r2), "=r"(r3) : "r"(a))

#define MBAR_INIT(a, c) asm volatile("mbarrier.init.shared.b64 [%0], %1;" :: "r"(a), "r"(c) : "memory")
#define MBAR_EXPECT(a, bytes) \
    asm volatile("mbarrier.arrive.expect_tx.shared.b64 _, [%0], %1;" :: "r"(a), "r"(bytes) : "memory")
#define CPBULK(dstS, srcG, bytes, mbar) \
    asm volatile("cp.async.bulk.shared::cta.global.mbarrier::complete_tx::bytes [%0], [%1], %2, [%3];" \
        :: "r"(dstS), "l"(__cvta_generic_to_global(srcG)), "r"(bytes), "r"(mbar) : "memory")
#define MBAR_WAIT(mbar_addr, parity) do { \
    uint32_t _m = (mbar_addr), _p = (parity), _d; \
    asm volatile("{\n\t.reg .pred p;\n\t" \
        "mbarrier.try_wait.parity.acquire.cta.shared::cta.b64 p, [%1], %2;\n\t" \
        "selp.b32 %0, 1, 0, p;\n\t}" : "=r"(_d) : "r"(_m), "r"(_p) : "memory"); \
    if (!_d) { \
        asm volatile("{\n\t.reg .pred P1;\n\t" \
            "WL_%=:\n\t" \
            "mbarrier.try_wait.parity.acquire.cta.shared::cta.b64 P1, [%0], %1, 0x989680;\n\t" \
            "@P1 bra.uni WD_%=;\n\t" \
            "bra.uni WL_%=;\n\t" \
            "WD_%=:\n\t}" :: "r"(_m), "r"(_p) : "memory"); \
    } \
} while (0)

__device__ __forceinline__ void mma16(float* d, const uint32_t* a, uint32_t b0, uint32_t b1) {
    asm volatile(
        "mma.sync.aligned.m16n8k16.row.col.f32.f16.f16.f32 "
        "{%0,%1,%2,%3}, {%4,%5,%6,%7}, {%8,%9}, {%0,%1,%2,%3};"
        : "+f"(d[0]), "+f"(d[1]), "+f"(d[2]), "+f"(d[3])
        : "r"(a[0]), "r"(a[1]), "r"(a[2]), "r"(a[3]), "r"(b0), "r"(b1));
}
__device__ __forceinline__ uint32_t packh2(float a, float b) {
    __half2 h = __floats2half2_rn(a, b);
    return *(uint32_t*)&h;
}
__device__ __forceinline__ float ex2f(float x) {
    float r;
    asm("ex2.approx.f32 %0, %1;" : "=f"(r) : "f"(x));
    return r;
}
#define L2E 1.4426950408889634f

// ---------------- fused prep + tokens transpose ----------------
#define TRANS_BLOCKS 8192
__global__ __launch_bounds__(256) void prep_kernel(
    const float* __restrict__ tokens,
    const float* __restrict__ kw, const float* __restrict__ kb, const float* __restrict__ kga,
    const float* __restrict__ kbe, const float* __restrict__ km, const float* __restrict__ kv,
    const float* __restrict__ qw, const float* __restrict__ qb, const float* __restrict__ qga,
    const float* __restrict__ qbe, const float* __restrict__ qm, const float* __restrict__ qv,
    const float* __restrict__ vw, const float* __restrict__ vb, const float* __restrict__ vga,
    const float* __restrict__ vbe, const float* __restrict__ vm, const float* __restrict__ vv,
    const float* __restrict__ fw, const float* __restrict__ fb, const float* __restrict__ fga,
    const float* __restrict__ fbe, const float* __restrict__ fm, const float* __restrict__ fv)
{
    __shared__ float tile[32][33];
    int t = threadIdx.x;
    if (blockIdx.x < TRANS_BLOCKS) {
        int bid = blockIdx.x;
        int l0 = (bid & 31) * 32, c0 = ((bid >> 5) & 31) * 32, n = bid >> 10;
#pragma unroll
        for (int i = 0; i < 4; ++i) {
            int idx = i * 256 + t;
            int r = idx >> 5, col = idx & 31;
            tile[r][col] = tokens[((size_t)(n * 1024 + c0 + r)) * 1024 + l0 + col];
        }
        __syncthreads();
#pragma unroll
        for (int i = 0; i < 4; ++i) {
            int idx = i * 256 + t;
            int r = idx >> 5, col = idx & 31;
            g_tokT[((size_t)(n * 1024 + l0 + r)) * 1024 + c0 + col] = __float2half(tile[col][r]);
        }
        return;
    }
    int id = (blockIdx.x - TRANS_BLOCKS) * 256 + t;
    if (id < 1024 * 1024) {
        int k = id & 1023, c = id >> 10;
        float inv = fga[c] * rsqrtf(fv[c] + 1e-5f);
        int cb = c >> 7, m = c & 127, kc = k >> 6, ch = (k >> 3) & 7, w = k & 7;
        size_t dst = ((size_t)((cb * 16 + kc) * 128 + m)) * 64 + ((ch ^ (m & 7)) << 3) + w;
        g_wfb[dst] = __float2half(fw[id] * inv);
        return;
    }
    int id2 = id - 1024 * 1024;
    if (id2 < 8 * 256 * 128) {
        int k = id2 & 127;
        int r = (id2 >> 7) & 255;
        int g = id2 >> 15;
        float w;
        if (r < 64) {
            int c = g * 64 + r;
            float inv = kga[c] * rsqrtf(kv[c] + 1e-5f);
            w = kw[c * 128 + k] * inv;
        } else if (r < 128) {
            int c = g * 64 + (r - 64);
            float inv = qga[c] * rsqrtf(qv[c] + 1e-5f);
            w = qw[c * 128 + k] * inv * (0.03125f * L2E);
        } else {
            int c = g * 128 + (r - 128);
            float inv = vga[c] * rsqrtf(vv[c] + 1e-5f);
            w = vw[c * 128 + k] * inv;
        }
        g_wg[id2] = __float2half(w);
        return;
    }
    int id3 = id2 - 8 * 256 * 128;
    if (id3 < 8 * 256) {
        int g = id3 >> 8, r = id3 & 255;
        float bias;
        if (r < 64) {
            int c = g * 64 + r;
            float inv = kga[c] * rsqrtf(kv[c] + 1e-5f);
            bias = kb[c] * inv + kbe[c] - km[c] * inv;
        } else if (r < 128) {
            int c = g * 64 + (r - 64);
            float inv = qga[c] * rsqrtf(qv[c] + 1e-5f);
            bias = (qb[c] * inv + qbe[c] - qm[c] * inv) * (0.03125f * L2E);
        } else {
            int c = g * 128 + (r - 128);
            float inv = vga[c] * rsqrtf(vv[c] + 1e-5f);
            bias = vb[c] * inv + vbe[c] - vm[c] * inv;
        }
        g_bg[id3] = bias;
        return;
    }
    int c = id3 - 8 * 256;
    if (c < 1024) {
        float inv = fga[c] * rsqrtf(fv[c] + 1e-5f);
        g_bf[c] = fb[c] * inv + fbe[c] - fm[c] * inv;
    }
}

// ---------------- GEMM pieces (fp16, ldmatrix, K-chunk 64, padded pitch) ----------------
#define TP64 144u
#define GTILE 18432u
#define GSTG  36864u
#define QKV_SMEM 73728
__device__ __forceinline__ void load_tile64(uint32_t dst, const __half* src, int stride_h, int t)
{
#pragma unroll
    for (int i = 0; i < 4; ++i) {
        int idx = i * 256 + t;
        int row = idx >> 3, c16 = idx & 7;
        CPA(dst + (uint32_t)row * TP64 + (uint32_t)c16 * 16u, src + (size_t)row * stride_h + c16 * 8);
    }
}

__device__ __forceinline__ void wgemm64(uint32_t As, uint32_t Bs, float C[4][4][4], int lane,
                                        int m0, int n0)
{
    int lr = (lane & 7) + ((lane >> 3) & 1) * 8;
    int akb = ((lane >> 4) & 1) * 8;
    int br = (lane & 7) + ((lane >> 4) & 1) * 8;
    int bkb = ((lane >> 3) & 1) * 8;
#pragma unroll
    for (int ks = 0; ks < 4; ++ks) {
        uint32_t a[4][4];
#pragma unroll
        for (int mi = 0; mi < 4; ++mi)
            LDSM4(a[mi][0], a[mi][1], a[mi][2], a[mi][3],
                  As + (uint32_t)(m0 + mi * 16 + lr) * TP64 + (uint32_t)((ks * 16 + akb) * 2));
#pragma unroll
        for (int np = 0; np < 2; ++np) {
            uint32_t b0, b1, b2, b3;
            LDSM4(b0, b1, b2, b3,
                  Bs + (uint32_t)(n0 + np * 16 + br) * TP64 + (uint32_t)((ks * 16 + bkb) * 2));
#pragma unroll
            for (int mi = 0; mi < 4; ++mi) {
                mma16(C[mi][np * 2], a[mi], b0, b1);
                mma16(C[mi][np * 2 + 1], a[mi], b2, b3);
            }
        }
    }
}

// ---------------- qkv conv GEMM (single-pass epilogue) ----------------
__global__ __launch_bounds__(256, 2) void qkv_tc()
{
    extern __shared__ float sm[];
    uint32_t sb = smem_u32(sm);
    int t = threadIdx.x, wid = t >> 5, lane = t & 31;
    int lt = blockIdx.x, rb = blockIdx.y, ng = blockIdx.z;
    int n = ng >> 3, g = ng & 7;
    int l0 = lt * 128;
    int m0 = (wid & 1) * 64, n0 = (wid >> 1) * 32;
    const __half* Ag = g_wg + (size_t)(g * 256 + rb * 128) * 128;
    const __half* Bg = g_tokT + ((size_t)(n * 1024 + l0)) * 1024 + g * 128;

    float C[4][4][4] = {};
    load_tile64(sb, Ag, 128, t);
    load_tile64(sb + GTILE, Bg, 1024, t);
    CPC();
    load_tile64(sb + GSTG, Ag + 64, 128, t);
    load_tile64(sb + GSTG + GTILE, Bg + 64, 1024, t);
    CPC();
    for (int c = 0; c < 2; ++c) {
        if (c == 0) CPW1(); else CPW0();
        __syncthreads();
        uint32_t As = sb + (uint32_t)c * GSTG;
        wgemm64(As, As + GTILE, C, lane, m0, n0);
    }
    __syncthreads();

    // single-pass: full 128x128 C in smem [128][132]
    float* Sb = sm;
    int r4 = lane >> 2, j = lane & 3;
#pragma unroll
    for (int mi = 0; mi < 4; ++mi)
#pragma unroll
        for (int ni = 0; ni < 4; ++ni) {
            int m = m0 + mi * 16 + r4;
            int q = n0 + ni * 8 + 2 * j;
            Sb[m * 132 + q] = C[mi][ni][0];
            Sb[m * 132 + q + 1] = C[mi][ni][1];
            Sb[(m + 8) * 132 + q] = C[mi][ni][2];
            Sb[(m + 8) * 132 + q + 1] = C[mi][ni][3];
        }
    __syncthreads();
    if (rb == 0) {
#pragma unroll
        for (int i = 0; i < 32; ++i) {
            int m = t & 63, l = (t >> 6) + 4 * i;
            int h = 2 * g + (m >> 5), d = m & 31;
            size_t base = (((size_t)(n * 16 + h)) * 1024 + l0 + l) * 32 + d;
            g_kbuf[base] = __float2half(Sb[m * 132 + l] + g_bg[g * 256 + m]);
            g_qbuf[base] = __float2half(Sb[(m + 64) * 132 + l] + g_bg[g * 256 + 64 + m]);
        }
    } else {
#pragma unroll
        for (int i = 0; i < 64; ++i) {
            int l = (t & 31) + 32 * (i >> 4), m = (t >> 5) + 8 * (i & 15);
            g_vbuf[((size_t)(n * 1024 + g * 128 + m)) * 1024 + l0 + l] =
                __float2half(Sb[m * 132 + l] + g_bg[g * 256 + 128 + m]);
        }
    }
}

// ---------------- ff conv: 128x128 tile, 512 thr (16 warps 4x4), bulk 3-stage (R15) ----------------
#define FA3 16384u
#define FSTG3 32768u
#define FCONV_SMEM 98304
#define SWA(row, ch) (((uint32_t)(row) << 7) + (uint32_t)(((ch) ^ ((row) & 7)) << 4))

__global__ __launch_bounds__(512, 2) void fconv_tc(float* __restrict__ out)
{
    extern __shared__ float sm[];
    uint32_t sb = smem_u32(sm);
    __shared__ __align__(8) uint64_t s_mbar[3];
    int t = threadIdx.x, wid = t >> 5, lane = t & 31;
    int lt = blockIdx.x, cb = blockIdx.y, n = blockIdx.z;
    int l0 = lt * 128;
    int m0 = (wid & 3) * 32, n0 = (wid >> 2) * 32;
    const __half* Ag = g_wfb + (size_t)(cb * 16) * 128 * 64;
    const __half* Bg = g_t2b + (size_t)(n * 16) * 1024 * 64 + (size_t)l0 * 64;

    if (t == 0) {
#pragma unroll
        for (int s = 0; s < 3; ++s) MBAR_INIT(smem_u32(&s_mbar[s]), 1);
    }
    __syncthreads();
    if (t == 0) {
#pragma unroll
        for (int c = 0; c < 2; ++c) {
            uint32_t mb = smem_u32(&s_mbar[c]);
            MBAR_EXPECT(mb, FSTG3);
            CPBULK(sb + (uint32_t)c * FSTG3, Ag + (size_t)c * 8192, FA3, mb);
            CPBULK(sb + (uint32_t)c * FSTG3 + FA3, Bg + (size_t)c * 65536, FA3, mb);
        }
    }

    float C[2][4][4] = {};
    int lr = (lane & 7) + ((lane >> 3) & 1) * 8;
    int akb8 = (lane >> 4) & 1;
    int br = (lane & 7) + ((lane >> 4) & 1) * 8;
    int bkb8 = (lane >> 3) & 1;

    for (int c = 0; c < 16; ++c) {
        int st = c % 3;
        MBAR_WAIT(smem_u32(&s_mbar[st]), (c / 3) & 1);
        __syncthreads();
        if (t == 0 && c + 2 < 16) {
            int nc = c + 2, ns = nc % 3;
            uint32_t mb = smem_u32(&s_mbar[ns]);
            MBAR_EXPECT(mb, FSTG3);
            CPBULK(sb + (uint32_t)ns * FSTG3, Ag + (size_t)nc * 8192, FA3, mb);
            CPBULK(sb + (uint32_t)ns * FSTG3 + FA3, Bg + (size_t)nc * 65536, FA3, mb);
        }
        uint32_t As = sb + (uint32_t)st * FSTG3;
        uint32_t Bs = As + FA3;
#pragma unroll
        for (int ks = 0; ks < 4; ++ks) {
            uint32_t a[2][4];
#pragma unroll
            for (int mi = 0; mi < 2; ++mi) {
                int row = m0 + mi * 16 + lr;
                LDSM4(a[mi][0], a[mi][1], a[mi][2], a[mi][3], As + SWA(row, ks * 2 + akb8));
            }
#pragma unroll
            for (int np = 0; np < 2; ++np) {
                int row = n0 + np * 16 + br;
                uint32_t b0, b1, b2, b3;
                LDSM4(b0, b1, b2, b3, Bs + SWA(row, ks * 2 + bkb8));
#pragma unroll
                for (int mi = 0; mi < 2; ++mi) {
                    mma16(C[mi][np * 2], a[mi], b0, b1);
                    mma16(C[mi][np * 2 + 1], a[mi], b2, b3);
                }
            }
        }
    }
    __syncthreads();

    float* Ob = sm;
    int r4 = lane >> 2, j = lane & 3;
#pragma unroll
    for (int mi = 0; mi < 2; ++mi)
#pragma unroll
        for (int ni = 0; ni < 4; ++ni) {
            int m = m0 + mi * 16 + r4;
            int q = n0 + ni * 8 + 2 * j;
            Ob[m * 133 + q] = C[mi][ni][0];
            Ob[m * 133 + q + 1] = C[mi][ni][1];
            Ob[(m + 8) * 133 + q] = C[mi][ni][2];
            Ob[(m + 8) * 133 + q + 1] = C[mi][ni][3];
        }
    __syncthreads();
#pragma unroll
    for (int i = 0; i < 32; ++i) {
        int idx = i * 512 + t;
        int m = idx >> 7, l = idx & 127;
        size_t addr = ((size_t)(n * 1024 + cb * 128 + m)) * 1024 + l0 + l;
        out[addr] = Ob[m * 133 + l] + g_bf[cb * 128 + m] + g_t2[addr];
    }
}

// ---------------- flash attention: 8-stage, 1 barrier per 4 tiles ----------------
#define TPK 80u
#define KST 5120u
#define AST 14336u
#define ATTN_SMEM 114688   // 8 stages

__device__ __forceinline__ void attn_load(uint32_t sb, const __half* Kg, const __half* Vg,
                                          int kt, int st, int t)
{
    uint32_t base = sb + (uint32_t)st * AST;
    int k0 = kt * 64;
    int row = t >> 2, c16 = t & 3;
    CPA(base + (uint32_t)row * TPK + (uint32_t)c16 * 16u, Kg + (size_t)(k0 + row) * 32 + c16 * 8);
#pragma unroll
    for (int i = 0; i < 2; ++i) {
        int idx = i * 256 + t;
        int vr = idx >> 3, vc = idx & 7;
        CPA(base + KST + (uint32_t)(vr * 144 + vc * 16), Vg + (size_t)vr * 1024 + k0 + vc * 8);
    }
    CPC();
}

__global__ __launch_bounds__(256, 2) void attn_tc(const float* __restrict__ tokens)
{
    extern __shared__ float sm[];
    uint32_t sb = smem_u32(sm);

    int t = threadIdx.x, wid = t >> 5, lane = t & 31;
    int r4 = lane >> 2, j = lane & 3;
    int qt = blockIdx.x, h = blockIdx.y, n = blockIdx.z;
    int q0g = qt * 128, q0w = wid * 16;
    const __half* Kg = g_kbuf + ((size_t)(n * 16 + h)) * 1024 * 32;
    const __half* Qg = g_qbuf + ((size_t)(n * 16 + h)) * 1024 * 32;
    const __half* Vg = g_vbuf + ((size_t)(n * 1024 + h * 64)) * 1024;

    uint32_t aq[2][4];
#pragma unroll
    for (int ds = 0; ds < 2; ++ds) {
        const __half* qb = Qg + (size_t)(q0g + q0w + r4) * 32 + ds * 16 + 2 * j;
        aq[ds][0] = *(const uint32_t*)qb;
        aq[ds][1] = *(const uint32_t*)(qb + 8 * 32);
        aq[ds][2] = *(const uint32_t*)(qb + 8);
        aq[ds][3] = *(const uint32_t*)(qb + 8 * 32 + 8);
    }

    // prologue: tiles 0..3 into stages 0..3
#pragma unroll
    for (int kt = 0; kt < 4; ++kt) attn_load(sb, Kg, Vg, kt, kt, t);

    float CO[8][4] = {};
    float l0 = 0.f, l1 = 0.f;
    int lr = (lane & 7) + ((lane >> 4) & 1) * 8;
    int kbo = ((lane >> 3) & 1) * 8;

    for (int pr = 0; pr < 4; ++pr) {
        CPW0();
        __syncthreads();
        if (pr < 3) {
#pragma unroll
            for (int s = 0; s < 4; ++s) {
                int kt = 4 * pr + 4 + s;
                attn_load(sb, Kg, Vg, kt, kt & 7, t);
            }
        }
#pragma unroll
        for (int sub = 0; sub < 4; ++sub) {
            int kt = 4 * pr + sub;
            uint32_t ksm = sb + (uint32_t)(kt & 7) * AST;
            uint32_t vsm = ksm + KST;

            float CS[8][4] = {};
#pragma unroll
            for (int ds = 0; ds < 2; ++ds)
#pragma unroll
                for (int ntp = 0; ntp < 4; ++ntp) {
                    uint32_t b0, b1, b2, b3;
                    LDSM4(b0, b1, b2, b3,
                          ksm + (uint32_t)(ntp * 16 + lr) * TPK + (uint32_t)((ds * 16 + kbo) * 2));
                    mma16(CS[2 * ntp], aq[ds], b0, b1);
                    mma16(CS[2 * ntp + 1], aq[ds], b2, b3);
                }

#pragma unroll
            for (int nt = 0; nt < 8; ++nt) {
                float e0 = ex2f(CS[nt][0]);
                float e1 = ex2f(CS[nt][1]);
                float e2 = ex2f(CS[nt][2]);
                float e3 = ex2f(CS[nt][3]);
                l0 += e0 + e1; l1 += e2 + e3;
                CS[nt][0] = e0; CS[nt][1] = e1; CS[nt][2] = e2; CS[nt][3] = e3;
            }

#pragma unroll
            for (int kc = 0; kc < 4; ++kc) {
                uint32_t ap[4];
                ap[0] = packh2(CS[2 * kc][0], CS[2 * kc][1]);
                ap[1] = packh2(CS[2 * kc][2], CS[2 * kc][3]);
                ap[2] = packh2(CS[2 * kc + 1][0], CS[2 * kc + 1][1]);
                ap[3] = packh2(CS[2 * kc + 1][2], CS[2 * kc + 1][3]);
#pragma unroll
                for (int ntp = 0; ntp < 4; ++ntp) {
                    uint32_t b0, b1, b2, b3;
                    LDSM4(b0, b1, b2, b3,
                          vsm + (uint32_t)((ntp * 16 + lr) * 144 + (kc * 16 + kbo) * 2));
                    mma16(CO[2 * ntp], ap, b0, b1);
                    mma16(CO[2 * ntp + 1], ap, b2, b3);
                }
            }
        }
    }

    l0 += __shfl_xor_sync(0xffffffffu, l0, 1);
    l0 += __shfl_xor_sync(0xffffffffu, l0, 2);
    l1 += __shfl_xor_sync(0xffffffffu, l1, 1);
    l1 += __shfl_xor_sync(0xffffffffu, l1, 2);

    __syncthreads();
    float* Ob = sm;  // [64][133]
    float li0 = 1.0f / l0, li1 = 1.0f / l1;
#pragma unroll
    for (int nt = 0; nt < 8; ++nt) {
        int d = nt * 8 + 2 * j;
        int q = q0w + r4;
        Ob[d * 133 + q] = CO[nt][0] * li0;
        Ob[(d + 1) * 133 + q] = CO[nt][1] * li0;
        Ob[d * 133 + q + 8] = CO[nt][2] * li1;
        Ob[(d + 1) * 133 + q + 8] = CO[nt][3] * li1;
    }
    __syncthreads();
#pragma unroll
    for (int i = 0; i < 32; ++i) {
        int q = t & 127, d = (t >> 7) + 2 * i;
        size_t addr = ((size_t)(n * 1024 + h * 64 + d)) * 1024 + q0g + q;
        float r = tokens[addr] + Ob[d * 133 + q];
        g_t2[addr] = r;
        Ob[d * 133 + q] = r;
    }
    __syncthreads();
#pragma unroll
    for (int i = 0; i < 32; ++i) {
        int d = t & 63, l = (t >> 6) + 4 * i;
        int lg = q0g + l;
        size_t dst = ((size_t)(n * 16 + h) * 1024 + lg) * 64 + (((d >> 3) ^ (lg & 7)) << 3) + (d & 7);
        g_t2b[dst] = __float2half(Ob[d * 133 + l]);
    }
}

// ---------------- launch ----------------
extern "C" void kernel_launch(void* const* d_in, const int* in_sizes, int n_in,
                              void* d_out, int out_size)
{
    (void)in_sizes; (void)n_in; (void)out_size;
    const float* tokens = (const float*)d_in[0];
    const float* p[24];
    for (int i = 0; i < 24; ++i) p[i] = (const float*)d_in[1 + i];

    cudaFuncSetAttribute(qkv_tc, cudaFuncAttributeMaxDynamicSharedMemorySize, QKV_SMEM);
    cudaFuncSetAttribute(fconv_tc, cudaFuncAttributeMaxDynamicSharedMemorySize, FCONV_SMEM);
    cudaFuncSetAttribute(attn_tc, cudaFuncAttributeMaxDynamicSharedMemorySize, ATTN_SMEM);

    int prep_blocks = TRANS_BLOCKS + (1024 * 1024 + 8 * 256 * 128 + 8 * 256 + 1024 + 255) / 256;
    prep_kernel<<<prep_blocks, 256>>>(tokens,
        p[0], p[1], p[2], p[3], p[4], p[5],
        p[6], p[7], p[8], p[9], p[10], p[11],
        p[12], p[13], p[14], p[15], p[16], p[17],
        p[18], p[19], p[20], p[21], p[22], p[23]);

    qkv_tc<<<dim3(8, 2, 64), 256, QKV_SMEM>>>();
    attn_tc<<<dim3(8, 16, 8), 256, ATTN_SMEM>>>(tokens);
    fconv_tc<<<dim3(8, 8, 8), 512, FCONV_SMEM>>>((float*)d_out);
}